// round 2
// baseline (speedup 1.0000x reference)
#include <cuda_runtime.h>
#include <cuda_bf16.h>
#include <math.h>

#define NE      30000
#define NREL    18
#define NB      8
#define D       128
#define NEDGE   1000000
#define BATCH   64
#define LSEQ    256
#define NCTX    32
#define NHEAD   2
#define DH      64
#define FFND    512
#define NLAY    2
#define NEGV    (-1e9f)

// ---------------- device scratch (static, referenced ONLY in device code) ---
static __device__ float g_W[(size_t)NREL * NE * D];     // 276 MB
static __device__ float g_kg[(size_t)NE * D];
static __device__ int   g_cnt[NE * NREL];
static __device__ float g_x [BATCH * LSEQ * D];
static __device__ float g_q [BATCH * LSEQ * D];
static __device__ float g_k [BATCH * LSEQ * D];
static __device__ float g_v [BATCH * LSEQ * D];
static __device__ float g_sc[(size_t)BATCH * NHEAD * LSEQ * LSEQ]; // 33.5MB
static __device__ float g_ao[BATCH * LSEQ * D];
static __device__ float g_tmp[BATCH * LSEQ * D];
static __device__ float g_ffn[BATCH * LSEQ * FFND];
static __device__ float g_trep[BATCH * D];
static __device__ float g_erep[BATCH * D];
static __device__ float g_user[BATCH * D];
static __device__ float* g_bufs[8];   // pointer table for GEMM operand selection

// buffer selector ids
#define BUF_X   0
#define BUF_Q   1
#define BUF_K   2
#define BUF_V   3
#define BUF_AO  4
#define BUF_TMP 5
#define BUF_FFN 6

__global__ void init_ptrs_kernel() {
    g_bufs[BUF_X] = g_x;  g_bufs[BUF_Q] = g_q;  g_bufs[BUF_K] = g_k;
    g_bufs[BUF_V] = g_v;  g_bufs[BUF_AO] = g_ao; g_bufs[BUF_TMP] = g_tmp;
    g_bufs[BUF_FFN] = g_ffn;
}

// ---------------- helpers ----------------
__device__ __forceinline__ float warp_sum(float v) {
    #pragma unroll
    for (int o = 16; o > 0; o >>= 1) v += __shfl_xor_sync(0xFFFFFFFFu, v, o);
    return v;
}
__device__ __forceinline__ float warp_max(float v) {
    #pragma unroll
    for (int o = 16; o > 0; o >>= 1) v = fmaxf(v, __shfl_xor_sync(0xFFFFFFFFu, v, o));
    return v;
}

// ---------------- RGCN ----------------
__global__ void __launch_bounds__(256) zero_cnt_kernel() {
    int i = blockIdx.x * blockDim.x + threadIdx.x;
    if (i < NE * NREL) g_cnt[i] = 0;
}

// W[r,n,d] = sum_b comp[r,b]*basis[b,n,d] ; kg init = root + bias
__global__ void __launch_bounds__(128) rgcn_w_kernel(const float* __restrict__ basis,
                                                     const float* __restrict__ comp,
                                                     const float* __restrict__ root,
                                                     const float* __restrict__ bias) {
    int n = blockIdx.x, d = threadIdx.x;
    __shared__ float sc[NREL * NB];
    for (int i = d; i < NREL * NB; i += 128) sc[i] = comp[i];
    __syncthreads();
    float bb[NB];
    #pragma unroll
    for (int q = 0; q < NB; q++) bb[q] = basis[((size_t)q * NE + n) * D + d];
    #pragma unroll
    for (int r = 0; r < NREL; r++) {
        float a = 0.f;
        #pragma unroll
        for (int q = 0; q < NB; q++) a = fmaf(sc[r * NB + q], bb[q], a);
        g_W[((size_t)r * NE + n) * D + d] = a;
    }
    g_kg[(size_t)n * D + d] = root[(size_t)n * D + d] + bias[d];
}

__global__ void __launch_bounds__(256) count_kernel(const int* __restrict__ ei,
                                                    const int* __restrict__ et) {
    int e = blockIdx.x * blockDim.x + threadIdx.x;
    if (e < NEDGE) atomicAdd(&g_cnt[ei[NEDGE + e] * NREL + et[e]], 1);
}

// one warp per edge: gather W row, scale by 1/cnt, vector-red into kg
__global__ void __launch_bounds__(256) scatter_kernel(const int* __restrict__ ei,
                                                      const int* __restrict__ et) {
    int w = (blockIdx.x * blockDim.x + threadIdx.x) >> 5;
    int lane = threadIdx.x & 31;
    if (w >= NEDGE) return;
    int src = ei[w], dst = ei[NEDGE + w], r = et[w];
    float norm = 1.f / fmaxf((float)g_cnt[dst * NREL + r], 1.f);
    const float4* wr = (const float4*)(g_W + ((size_t)r * NE + src) * D);
    float4 v = wr[lane];
    float* o = g_kg + (size_t)dst * D + lane * 4;
    asm volatile("red.global.add.v4.f32 [%0], {%1,%2,%3,%4};"
                 :: "l"(o), "f"(v.x * norm), "f"(v.y * norm), "f"(v.z * norm), "f"(v.w * norm)
                 : "memory");
}

// ---------------- encoder ----------------
__global__ void __launch_bounds__(256) embed_kernel(const int* __restrict__ tokens,
                                                    const float* __restrict__ tok_emb,
                                                    const float* __restrict__ pos_emb) {
    int i = blockIdx.x * blockDim.x + threadIdx.x;   // < B*L*D
    int d = i & (D - 1);
    int bl = i >> 7;
    int l = bl & (LSEQ - 1);
    int tk = tokens[bl];
    g_x[i] = tok_emb[(size_t)tk * D + d] * 11.3137084989847603904f + pos_emb[l * D + d];
}

// C[M,N] = act(A[M,K] @ B[K,N] + bias). A,C selected from g_bufs.
// 256 threads, 128x128 tile, 8x8 per thread (split 4+4 layout).
__global__ void __launch_bounds__(256) gemm_kernel(const float* __restrict__ Bw,
                                                   const float* __restrict__ bias,
                                                   int asel, int csel,
                                                   int M, int N, int K, int relu) {
    const float* __restrict__ A = g_bufs[asel];
    float* __restrict__ C = g_bufs[csel];
    __shared__ float As[16][128];
    __shared__ float Bs[16][128];
    int m0 = blockIdx.x * 128, n0 = blockIdx.y * 128;
    int tid = threadIdx.x;
    int ty = tid >> 4, tx = tid & 15;
    float acc[8][8];
    #pragma unroll
    for (int i = 0; i < 8; i++)
        #pragma unroll
        for (int j = 0; j < 8; j++) acc[i][j] = 0.f;

    int a_r = tid >> 1, a_k = (tid & 1) * 8;
    int b_k = tid >> 4, b_n = (tid & 15) * 8;

    for (int kc = 0; kc < K; kc += 16) {
        const float* ap = A + (size_t)(m0 + a_r) * K + kc + a_k;
        float4 av0 = *(const float4*)ap;
        float4 av1 = *(const float4*)(ap + 4);
        As[a_k + 0][a_r] = av0.x; As[a_k + 1][a_r] = av0.y;
        As[a_k + 2][a_r] = av0.z; As[a_k + 3][a_r] = av0.w;
        As[a_k + 4][a_r] = av1.x; As[a_k + 5][a_r] = av1.y;
        As[a_k + 6][a_r] = av1.z; As[a_k + 7][a_r] = av1.w;
        const float* bp = Bw + (size_t)(kc + b_k) * N + n0 + b_n;
        *(float4*)&Bs[b_k][b_n]     = *(const float4*)bp;
        *(float4*)&Bs[b_k][b_n + 4] = *(const float4*)(bp + 4);
        __syncthreads();
        #pragma unroll
        for (int kk = 0; kk < 16; kk++) {
            float4 a0 = *(const float4*)&As[kk][ty * 4];
            float4 a1 = *(const float4*)&As[kk][64 + ty * 4];
            float4 b0 = *(const float4*)&Bs[kk][tx * 4];
            float4 b1 = *(const float4*)&Bs[kk][64 + tx * 4];
            float avv[8] = {a0.x, a0.y, a0.z, a0.w, a1.x, a1.y, a1.z, a1.w};
            float bvv[8] = {b0.x, b0.y, b0.z, b0.w, b1.x, b1.y, b1.z, b1.w};
            #pragma unroll
            for (int i = 0; i < 8; i++)
                #pragma unroll
                for (int j = 0; j < 8; j++) acc[i][j] = fmaf(avv[i], bvv[j], acc[i][j]);
        }
        __syncthreads();
    }
    float bcol[8];
    #pragma unroll
    for (int j = 0; j < 8; j++) {
        int col = n0 + tx * 4 + (j & 3) + (j >> 2) * 64;
        bcol[j] = bias ? bias[col] : 0.f;
    }
    #pragma unroll
    for (int i = 0; i < 8; i++) {
        int row = m0 + ty * 4 + (i & 3) + (i >> 2) * 64;
        float c0 = acc[i][0] + bcol[0], c1 = acc[i][1] + bcol[1];
        float c2 = acc[i][2] + bcol[2], c3 = acc[i][3] + bcol[3];
        float c4 = acc[i][4] + bcol[4], c5 = acc[i][5] + bcol[5];
        float c6 = acc[i][6] + bcol[6], c7 = acc[i][7] + bcol[7];
        if (relu) {
            c0 = fmaxf(c0, 0.f); c1 = fmaxf(c1, 0.f); c2 = fmaxf(c2, 0.f); c3 = fmaxf(c3, 0.f);
            c4 = fmaxf(c4, 0.f); c5 = fmaxf(c5, 0.f); c6 = fmaxf(c6, 0.f); c7 = fmaxf(c7, 0.f);
        }
        *(float4*)&C[(size_t)row * N + n0 + tx * 4]      = make_float4(c0, c1, c2, c3);
        *(float4*)&C[(size_t)row * N + n0 + 64 + tx * 4] = make_float4(c4, c5, c6, c7);
    }
}

// scores[bh,q,k] = (q.k)/8 + mask ; tile 32q x 128k, K=64
__global__ void __launch_bounds__(256) attn_scores_kernel(const int* __restrict__ tokens) {
    int bh = blockIdx.x;
    int b = bh >> 1, h = bh & 1;
    int q0 = blockIdx.y * 32, k0 = blockIdx.z * 128;
    __shared__ float Qs[64][32];
    __shared__ float Ks[64][128];
    int tid = threadIdx.x;
    {
        int r = tid & 31, ds = (tid >> 5) * 8;
        const float* src = g_q + ((size_t)(b * LSEQ + q0 + r)) * D + h * DH + ds;
        #pragma unroll
        for (int i = 0; i < 8; i++) Qs[ds + i][r] = src[i];
    }
    {
        int r = tid >> 1, ds = (tid & 1) * 32;
        const float* src = g_k + ((size_t)(b * LSEQ + k0 + r)) * D + h * DH + ds;
        #pragma unroll
        for (int i = 0; i < 32; i++) Ks[ds + i][r] = src[i];
    }
    __syncthreads();
    int w = tid >> 5, lane = tid & 31;
    float acc[4][4];
    #pragma unroll
    for (int i = 0; i < 4; i++)
        #pragma unroll
        for (int j = 0; j < 4; j++) acc[i][j] = 0.f;
    #pragma unroll 4
    for (int d = 0; d < 64; d++) {
        float4 qv = *(const float4*)&Qs[d][w * 4];
        float4 kv = *(const float4*)&Ks[d][lane * 4];
        float qa[4] = {qv.x, qv.y, qv.z, qv.w};
        float ka[4] = {kv.x, kv.y, kv.z, kv.w};
        #pragma unroll
        for (int i = 0; i < 4; i++)
            #pragma unroll
            for (int j = 0; j < 4; j++) acc[i][j] = fmaf(qa[i], ka[j], acc[i][j]);
    }
    float mbias[4];
    #pragma unroll
    for (int j = 0; j < 4; j++)
        mbias[j] = (tokens[b * LSEQ + k0 + lane * 4 + j] != 0) ? 0.f : NEGV;
    #pragma unroll
    for (int i = 0; i < 4; i++) {
        int ql = q0 + w * 4 + i;
        float4 o = make_float4(acc[i][0] * 0.125f + mbias[0], acc[i][1] * 0.125f + mbias[1],
                               acc[i][2] * 0.125f + mbias[2], acc[i][3] * 0.125f + mbias[3]);
        *(float4*)&g_sc[((size_t)(bh * LSEQ + ql)) * LSEQ + k0 + lane * 4] = o;
    }
}

// row softmax over 256, one warp per row
__global__ void __launch_bounds__(128) softmax_kernel() {
    int row = blockIdx.x * 4 + (threadIdx.x >> 5);
    int lane = threadIdx.x & 31;
    float* p = g_sc + (size_t)row * LSEQ;
    float v[8];
    float m = -INFINITY;
    #pragma unroll
    for (int i = 0; i < 8; i++) { v[i] = p[lane + 32 * i]; m = fmaxf(m, v[i]); }
    m = warp_max(m);
    float s = 0.f;
    #pragma unroll
    for (int i = 0; i < 8; i++) { v[i] = expf(v[i] - m); s += v[i]; }
    s = warp_sum(s);
    float inv = 1.f / s;
    #pragma unroll
    for (int i = 0; i < 8; i++) p[lane + 32 * i] = v[i] * inv;
}

// o[b,l,h*64+d] = sum_kl a[bh,l,kl] * v[b,kl,h*64+d]
__global__ void __launch_bounds__(256) attn_av_kernel() {
    int bh = blockIdx.x;
    int b = bh >> 1, h = bh & 1;
    int l0 = blockIdx.y * 64;
    __shared__ float Ast[64][68];
    __shared__ float Vs[64][64];
    int tid = threadIdx.x;
    int ty = tid >> 4, tx = tid & 15;
    float acc[4][4];
    #pragma unroll
    for (int i = 0; i < 4; i++)
        #pragma unroll
        for (int j = 0; j < 4; j++) acc[i][j] = 0.f;
    int lr = tid >> 2, lc = (tid & 3) * 16;
    for (int kc = 0; kc < 4; kc++) {
        const float* ap = g_sc + ((size_t)(bh * LSEQ + l0 + lr)) * LSEQ + kc * 64 + lc;
        #pragma unroll
        for (int u = 0; u < 4; u++) {
            float4 t = *(const float4*)(ap + u * 4);
            Ast[lc + u * 4 + 0][lr] = t.x; Ast[lc + u * 4 + 1][lr] = t.y;
            Ast[lc + u * 4 + 2][lr] = t.z; Ast[lc + u * 4 + 3][lr] = t.w;
        }
        const float* vp = g_v + ((size_t)(b * LSEQ + kc * 64 + lr)) * D + h * DH + lc;
        #pragma unroll
        for (int u = 0; u < 4; u++)
            *(float4*)&Vs[lr][lc + u * 4] = *(const float4*)(vp + u * 4);
        __syncthreads();
        #pragma unroll 4
        for (int kl = 0; kl < 64; kl++) {
            float4 av = *(const float4*)&Ast[kl][ty * 4];
            float4 vv = *(const float4*)&Vs[kl][tx * 4];
            float aa[4] = {av.x, av.y, av.z, av.w};
            float bb[4] = {vv.x, vv.y, vv.z, vv.w};
            #pragma unroll
            for (int i = 0; i < 4; i++)
                #pragma unroll
                for (int j = 0; j < 4; j++) acc[i][j] = fmaf(aa[i], bb[j], acc[i][j]);
        }
        __syncthreads();
    }
    #pragma unroll
    for (int i = 0; i < 4; i++) {
        float4 ov = make_float4(acc[i][0], acc[i][1], acc[i][2], acc[i][3]);
        *(float4*)&g_ao[((size_t)(b * LSEQ + l0 + ty * 4 + i)) * D + h * DH + tx * 4] = ov;
    }
}

// x = LN(x + tmp) * g + b
__global__ void __launch_bounds__(128) add_ln_kernel(const float* __restrict__ g,
                                                     const float* __restrict__ b) {
    int row = blockIdx.x, tid = threadIdx.x;
    int w = tid >> 5, lane = tid & 31;
    float v = g_x[(size_t)row * D + tid] + g_tmp[(size_t)row * D + tid];
    float s = warp_sum(v);
    float s2 = warp_sum(v * v);
    __shared__ float ws[4], ws2[4];
    if (lane == 0) { ws[w] = s; ws2[w] = s2; }
    __syncthreads();
    s = ws[0] + ws[1] + ws[2] + ws[3];
    s2 = ws2[0] + ws2[1] + ws2[2] + ws2[3];
    float m = s * (1.f / D);
    float var = s2 * (1.f / D) - m * m;
    float inv = rsqrtf(var + 1e-5f);
    g_x[(size_t)row * D + tid] = (v - m) * inv * g[tid] + b[tid];
}

// ---------------- pooling / gate / final ----------------
// uses g_ffn = x @ tok_Wa + ba  (precomputed by gemm), g_x for the weighted sum
__global__ void __launch_bounds__(128) tok_pool_kernel(const int* __restrict__ tokens,
                                                       const float* __restrict__ vvec) {
    int b = blockIdx.x, tid = threadIdx.x;
    int w = tid >> 5, lane = tid & 31;
    __shared__ float s_s[LSEQ];
    __shared__ float red[4];
    for (int l = w; l < LSEQ; l += 4) {
        float val = 0.f;
        #pragma unroll
        for (int d = lane; d < D; d += 32)
            val += tanhf(g_ffn[((size_t)(b * LSEQ + l)) * D + d]) * vvec[d];
        val = warp_sum(val);
        if (lane == 0) s_s[l] = (tokens[b * LSEQ + l] != 0) ? val : NEGV;
    }
    __syncthreads();
    float m = fmaxf(s_s[tid], s_s[tid + 128]);
    m = warp_max(m);
    if (lane == 0) red[w] = m;
    __syncthreads();
    m = fmaxf(fmaxf(red[0], red[1]), fmaxf(red[2], red[3]));
    __syncthreads();
    float e0 = expf(s_s[tid] - m), e1 = expf(s_s[tid + 128] - m);
    float ssum = warp_sum(e0 + e1);
    if (lane == 0) red[w] = ssum;
    __syncthreads();
    ssum = red[0] + red[1] + red[2] + red[3];
    float inv = 1.f / ssum;
    __syncthreads();
    s_s[tid] = e0 * inv; s_s[tid + 128] = e1 * inv;
    __syncthreads();
    float acc = 0.f;
    for (int l = 0; l < LSEQ; l++)
        acc = fmaf(s_s[l], g_x[((size_t)(b * LSEQ + l)) * D + tid], acc);
    g_trep[b * D + tid] = acc;
}

__global__ void __launch_bounds__(128) ent_pool_kernel(const int* __restrict__ ctx,
                                                       const float* __restrict__ Wa,
                                                       const float* __restrict__ ba,
                                                       const float* __restrict__ vvec) {
    int b = blockIdx.x, tid = threadIdx.x;
    int w = tid >> 5, lane = tid & 31;
    __shared__ float h_s[NCTX][D];
    __shared__ float s_s[NCTX];
    __shared__ int cs[NCTX];
    if (tid < NCTX) cs[tid] = ctx[b * NCTX + tid];
    __syncthreads();
    for (int j = 0; j < NCTX; j++)
        h_s[j][tid] = g_kg[(size_t)cs[j] * D + tid];
    __syncthreads();
    for (int j = w; j < NCTX; j += 4) {
        float val = 0.f;
        for (int d = lane; d < D; d += 32) {
            float acc = ba[d];
            #pragma unroll 8
            for (int kk = 0; kk < D; kk++)
                acc = fmaf(h_s[j][kk], Wa[kk * D + d], acc);
            val += tanhf(acc) * vvec[d];
        }
        val = warp_sum(val);
        if (lane == 0) s_s[j] = (cs[j] != 0) ? val : NEGV;
    }
    __syncthreads();
    if (w == 0) {
        float sv = s_s[lane];
        float m = warp_max(sv);
        float e = expf(sv - m);
        float ssum = warp_sum(e);
        s_s[lane] = e / ssum;
    }
    __syncthreads();
    float acc = 0.f;
    #pragma unroll
    for (int j = 0; j < NCTX; j++) acc = fmaf(s_s[j], h_s[j][tid], acc);
    g_erep[b * D + tid] = acc;
}

__global__ void __launch_bounds__(128) gate_kernel(const float* __restrict__ Wg,
                                                   const float* __restrict__ bg) {
    int b = blockIdx.x, tid = threadIdx.x;
    __shared__ float cat[2 * D];
    cat[tid] = g_trep[b * D + tid];
    cat[D + tid] = g_erep[b * D + tid];
    __syncthreads();
    float acc = bg[tid];
    #pragma unroll 8
    for (int j = 0; j < 2 * D; j++) acc = fmaf(cat[j], Wg[j * D + tid], acc);
    float sg = 1.f / (1.f + expf(-acc));
    g_user[b * D + tid] = sg * cat[tid] + (1.f - sg) * cat[D + tid];
}

// out[b,n] = user[b,:] . kg[n,:]
__global__ void __launch_bounds__(256) final_kernel(float* __restrict__ out) {
    __shared__ float kg_s[128][17];
    __shared__ float user_t[D][BATCH];
    int n0 = blockIdx.x * 128, tid = threadIdx.x;
    for (int i = tid; i < D * BATCH; i += 256) {
        int d = i >> 6, bb = i & 63;
        user_t[d][bb] = g_user[bb * D + d];
    }
    int tn = tid >> 3, tb = tid & 7;
    float acc[4][8];
    #pragma unroll
    for (int i = 0; i < 4; i++)
        #pragma unroll
        for (int j = 0; j < 8; j++) acc[i][j] = 0.f;
    for (int dc = 0; dc < D; dc += 16) {
        __syncthreads();
        for (int i = tid; i < 128 * 16; i += 256) {
            int nl = i >> 4, dd = i & 15;
            int n = n0 + nl;
            kg_s[nl][dd] = (n < NE) ? g_kg[(size_t)n * D + dc + dd] : 0.f;
        }
        __syncthreads();
        #pragma unroll
        for (int dd = 0; dd < 16; dd++) {
            float kv[4], uv[8];
            #pragma unroll
            for (int i = 0; i < 4; i++) kv[i] = kg_s[tn * 4 + i][dd];
            #pragma unroll
            for (int j = 0; j < 8; j++) uv[j] = user_t[dc + dd][tb * 8 + j];
            #pragma unroll
            for (int i = 0; i < 4; i++)
                #pragma unroll
                for (int j = 0; j < 8; j++) acc[i][j] = fmaf(kv[i], uv[j], acc[i][j]);
        }
    }
    #pragma unroll
    for (int i = 0; i < 4; i++) {
        int n = n0 + tn * 4 + i;
        if (n < NE) {
            #pragma unroll
            for (int j = 0; j < 8; j++)
                out[(size_t)(tb * 8 + j) * NE + n] = acc[i][j];
        }
    }
}

// ---------------- launch ----------------
extern "C" void kernel_launch(void* const* d_in, const int* in_sizes, int n_in,
                              void* d_out, int out_size) {
    const int*   edge_idx = (const int*)d_in[0];
    const int*   edge_type = (const int*)d_in[1];
    const int*   ctx_ent  = (const int*)d_in[2];
    const int*   ctx_tok  = (const int*)d_in[3];
    const float* basis    = (const float*)d_in[4];
    const float* comp     = (const float*)d_in[5];
    const float* root     = (const float*)d_in[6];
    const float* rgcn_b   = (const float*)d_in[7];
    const float* tok_emb  = (const float*)d_in[8];
    const float* pos_emb  = (const float*)d_in[9];
    const float* Wqkv     = (const float*)d_in[10];
    const float* Wo       = (const float*)d_in[11];
    const float* ln1_g    = (const float*)d_in[12];
    const float* ln1_b    = (const float*)d_in[13];
    const float* ln2_g    = (const float*)d_in[14];
    const float* ln2_b    = (const float*)d_in[15];
    const float* W1       = (const float*)d_in[16];
    const float* b1       = (const float*)d_in[17];
    const float* W2       = (const float*)d_in[18];
    const float* b2       = (const float*)d_in[19];
    const float* ent_Wa   = (const float*)d_in[20];
    const float* ent_ba   = (const float*)d_in[21];
    const float* ent_v    = (const float*)d_in[22];
    const float* tok_Wa   = (const float*)d_in[23];
    const float* tok_ba   = (const float*)d_in[24];
    const float* tok_v    = (const float*)d_in[25];
    const float* Wg       = (const float*)d_in[26];
    const float* bg       = (const float*)d_in[27];
    float* out = (float*)d_out;

    init_ptrs_kernel<<<1, 1>>>();

    // --- RGCN ---
    zero_cnt_kernel<<<(NE * NREL + 255) / 256, 256>>>();
    rgcn_w_kernel<<<NE, 128>>>(basis, comp, root, rgcn_b);
    count_kernel<<<(NEDGE + 255) / 256, 256>>>(edge_idx, edge_type);
    scatter_kernel<<<NEDGE / 8, 256>>>(edge_idx, edge_type);

    // --- encoder ---
    embed_kernel<<<(BATCH * LSEQ * D) / 256, 256>>>(ctx_tok, tok_emb, pos_emb);
    const int M = BATCH * LSEQ;  // 16384
    for (int l = 0; l < NLAY; l++) {
        gemm_kernel<<<dim3(M / 128, 1), 256>>>(Wqkv + (size_t)(l * 3 + 0) * D * D, nullptr, BUF_X, BUF_Q, M, D, D, 0);
        gemm_kernel<<<dim3(M / 128, 1), 256>>>(Wqkv + (size_t)(l * 3 + 1) * D * D, nullptr, BUF_X, BUF_K, M, D, D, 0);
        gemm_kernel<<<dim3(M / 128, 1), 256>>>(Wqkv + (size_t)(l * 3 + 2) * D * D, nullptr, BUF_X, BUF_V, M, D, D, 0);
        attn_scores_kernel<<<dim3(BATCH * NHEAD, LSEQ / 32, LSEQ / 128), 256>>>(ctx_tok);
        softmax_kernel<<<(BATCH * NHEAD * LSEQ) / 4, 128>>>();
        attn_av_kernel<<<dim3(BATCH * NHEAD, LSEQ / 64), 256>>>();
        gemm_kernel<<<dim3(M / 128, 1), 256>>>(Wo + (size_t)l * D * D, nullptr, BUF_AO, BUF_TMP, M, D, D, 0);
        add_ln_kernel<<<M, 128>>>(ln1_g + l * D, ln1_b + l * D);
        gemm_kernel<<<dim3(M / 128, FFND / 128), 256>>>(W1 + (size_t)l * D * FFND, b1 + l * FFND, BUF_X, BUF_FFN, M, FFND, D, 1);
        gemm_kernel<<<dim3(M / 128, 1), 256>>>(W2 + (size_t)l * FFND * D, b2 + l * D, BUF_FFN, BUF_TMP, M, D, FFND, 0);
        add_ln_kernel<<<M, 128>>>(ln2_g + l * D, ln2_b + l * D);
    }

    // --- pooling / gate / score ---
    gemm_kernel<<<dim3(M / 128, 1), 256>>>(tok_Wa, tok_ba, BUF_X, BUF_FFN, M, D, D, 0);
    tok_pool_kernel<<<BATCH, 128>>>(ctx_tok, tok_v);
    ent_pool_kernel<<<BATCH, 128>>>(ctx_ent, ent_ba ? ent_Wa : ent_Wa, ent_ba, ent_v);
    gate_kernel<<<BATCH, 128>>>(Wg, bg);
    final_kernel<<<(NE + 127) / 128, 256>>>(out);
}

// round 4
// speedup vs baseline: 1.1451x; 1.1451x over previous
#include <cuda_runtime.h>
#include <cuda_bf16.h>
#include <math.h>

#define NE      30000
#define NREL    18
#define NB      8
#define D       128
#define NEDGE   1000000
#define BATCH   64
#define LSEQ    256
#define NCTX    32
#define NHEAD   2
#define DH      64
#define FFND    512
#define NLAY    2
#define NEGV    (-1e9f)

// ---------------- device scratch (static, referenced ONLY in device code) ---
static __device__ float g_W[(size_t)NREL * NE * D];     // 276 MB
static __device__ float g_kg[(size_t)NE * D];
static __device__ int   g_cnt[NE * NREL];
static __device__ float g_x [BATCH * LSEQ * D];
static __device__ float g_q [BATCH * LSEQ * D];
static __device__ float g_k [BATCH * LSEQ * D];
static __device__ float g_v [BATCH * LSEQ * D];
static __device__ float g_sc[(size_t)BATCH * NHEAD * LSEQ * LSEQ]; // 33.5MB
static __device__ float g_ao[BATCH * LSEQ * D];
static __device__ float g_tmp[BATCH * LSEQ * D];
static __device__ float g_ffn[BATCH * LSEQ * FFND];
static __device__ float g_trep[BATCH * D];
static __device__ float g_erep[BATCH * D];
static __device__ float g_user[BATCH * D];
static __device__ float* g_bufs[8];

#define BUF_X   0
#define BUF_Q   1
#define BUF_K   2
#define BUF_V   3
#define BUF_AO  4
#define BUF_TMP 5
#define BUF_FFN 6

__global__ void init_ptrs_kernel() {
    g_bufs[BUF_X] = g_x;  g_bufs[BUF_Q] = g_q;  g_bufs[BUF_K] = g_k;
    g_bufs[BUF_V] = g_v;  g_bufs[BUF_AO] = g_ao; g_bufs[BUF_TMP] = g_tmp;
    g_bufs[BUF_FFN] = g_ffn;
}

// ---------------- helpers ----------------
__device__ __forceinline__ float warp_sum(float v) {
    #pragma unroll
    for (int o = 16; o > 0; o >>= 1) v += __shfl_xor_sync(0xFFFFFFFFu, v, o);
    return v;
}
__device__ __forceinline__ float warp_max(float v) {
    #pragma unroll
    for (int o = 16; o > 0; o >>= 1) v = fmaxf(v, __shfl_xor_sync(0xFFFFFFFFu, v, o));
    return v;
}
__device__ __forceinline__ void mma_tf32(float* c, const unsigned* a, const unsigned* b) {
    asm volatile(
        "mma.sync.aligned.m16n8k8.row.col.f32.tf32.tf32.f32 "
        "{%0,%1,%2,%3}, {%4,%5,%6,%7}, {%8,%9}, {%0,%1,%2,%3};\n"
        : "+f"(c[0]), "+f"(c[1]), "+f"(c[2]), "+f"(c[3])
        : "r"(a[0]), "r"(a[1]), "r"(a[2]), "r"(a[3]), "r"(b[0]), "r"(b[1]));
}

// ---------------- RGCN ----------------
__global__ void __launch_bounds__(256) zero_cnt_kernel() {
    int i = blockIdx.x * blockDim.x + threadIdx.x;
    if (i < NE * NREL) g_cnt[i] = 0;
}

__global__ void __launch_bounds__(128) rgcn_w_kernel(const float* __restrict__ basis,
                                                     const float* __restrict__ comp,
                                                     const float* __restrict__ root,
                                                     const float* __restrict__ bias) {
    int n = blockIdx.x, d = threadIdx.x;
    __shared__ float sc[NREL * NB];
    for (int i = d; i < NREL * NB; i += 128) sc[i] = comp[i];
    __syncthreads();
    float bb[NB];
    #pragma unroll
    for (int q = 0; q < NB; q++) bb[q] = basis[((size_t)q * NE + n) * D + d];
    #pragma unroll
    for (int r = 0; r < NREL; r++) {
        float a = 0.f;
        #pragma unroll
        for (int q = 0; q < NB; q++) a = fmaf(sc[r * NB + q], bb[q], a);
        g_W[((size_t)r * NE + n) * D + d] = a;
    }
    g_kg[(size_t)n * D + d] = root[(size_t)n * D + d] + bias[d];
}

__global__ void __launch_bounds__(256) count_kernel(const int* __restrict__ ei,
                                                    const int* __restrict__ et) {
    int e = blockIdx.x * blockDim.x + threadIdx.x;
    if (e < NEDGE) atomicAdd(&g_cnt[ei[NEDGE + e] * NREL + et[e]], 1);
}

__global__ void __launch_bounds__(256) scatter_kernel(const int* __restrict__ ei,
                                                      const int* __restrict__ et) {
    int w = (blockIdx.x * blockDim.x + threadIdx.x) >> 5;
    int lane = threadIdx.x & 31;
    if (w >= NEDGE) return;
    int src = ei[w], dst = ei[NEDGE + w], r = et[w];
    float norm = 1.f / fmaxf((float)g_cnt[dst * NREL + r], 1.f);
    const float4* wr = (const float4*)(g_W + ((size_t)r * NE + src) * D);
    float4 v = wr[lane];
    float* o = g_kg + (size_t)dst * D + lane * 4;
    asm volatile("red.global.add.v4.f32 [%0], {%1,%2,%3,%4};"
                 :: "l"(o), "f"(v.x * norm), "f"(v.y * norm), "f"(v.z * norm), "f"(v.w * norm)
                 : "memory");
}

// ---------------- encoder ----------------
__global__ void __launch_bounds__(256) embed_kernel(const int* __restrict__ tokens,
                                                    const float* __restrict__ tok_emb,
                                                    const float* __restrict__ pos_emb) {
    int i = blockIdx.x * blockDim.x + threadIdx.x;
    int d = i & (D - 1);
    int bl = i >> 7;
    int l = bl & (LSEQ - 1);
    int tk = tokens[bl];
    g_x[i] = tok_emb[(size_t)tk * D + d] * 11.3137084989847603904f + pos_emb[l * D + d];
}

// ---- tf32 tensor-core GEMM: C[M,N] = act(A@B + bias) ----
// 128x128 tile, BK=16, 8 warps (4x2), warp tile 32x64 of m16n8k8 frags.
__global__ void __launch_bounds__(256) gemm_tc_kernel(const float* __restrict__ Bw,
                                                      const float* __restrict__ bias,
                                                      int asel, int csel,
                                                      int M, int N, int K, int relu) {
    const float* __restrict__ A = g_bufs[asel];
    float* __restrict__ C = g_bufs[csel];
    __shared__ float As[16][136];   // [k][m], stride 136 -> conflict-free frag loads
    __shared__ float Bs[16][136];   // [k][n]
    int m0 = blockIdx.x * 128, n0 = blockIdx.y * 128;
    int tid = threadIdx.x;
    int wid = tid >> 5, lane = tid & 31;
    int wm = wid & 3, wn = wid >> 2;          // warp grid 4 (m) x 2 (n)
    int g = lane >> 2, t4 = lane & 3;

    float acc[2][8][4];
    #pragma unroll
    for (int i = 0; i < 2; i++)
        #pragma unroll
        for (int j = 0; j < 8; j++)
            #pragma unroll
            for (int q = 0; q < 4; q++) acc[i][j][q] = 0.f;

    int ar = tid >> 1, ak = (tid & 1) * 8;    // A fill: row ar, cols ak..ak+7
    int bk = tid >> 4, bn = (tid & 15) * 8;   // B fill: row bk, cols bn..bn+7

    for (int kc = 0; kc < K; kc += 16) {
        const float* ap = A + (size_t)(m0 + ar) * K + kc + ak;
        float4 av0 = *(const float4*)ap;
        float4 av1 = *(const float4*)(ap + 4);
        As[ak + 0][ar] = av0.x; As[ak + 1][ar] = av0.y;
        As[ak + 2][ar] = av0.z; As[ak + 3][ar] = av0.w;
        As[ak + 4][ar] = av1.x; As[ak + 5][ar] = av1.y;
        As[ak + 6][ar] = av1.z; As[ak + 7][ar] = av1.w;
        const float* bp = Bw + (size_t)(kc + bk) * N + n0 + bn;
        *(float4*)&Bs[bk][bn]     = *(const float4*)bp;
        *(float4*)&Bs[bk][bn + 4] = *(const float4*)(bp + 4);
        __syncthreads();
        #pragma unroll
        for (int ks = 0; ks < 16; ks += 8) {
            unsigned af[2][4], bf[8][2];
            int mb = wm * 32;
            #pragma unroll
            for (int mf = 0; mf < 2; mf++) {
                int mm = mb + mf * 16;
                af[mf][0] = __float_as_uint(As[ks + t4    ][mm + g    ]);
                af[mf][1] = __float_as_uint(As[ks + t4    ][mm + g + 8]);
                af[mf][2] = __float_as_uint(As[ks + t4 + 4][mm + g    ]);
                af[mf][3] = __float_as_uint(As[ks + t4 + 4][mm + g + 8]);
            }
            #pragma unroll
            for (int nf = 0; nf < 8; nf++) {
                int nn = wn * 64 + nf * 8 + g;
                bf[nf][0] = __float_as_uint(Bs[ks + t4    ][nn]);
                bf[nf][1] = __float_as_uint(Bs[ks + t4 + 4][nn]);
            }
            #pragma unroll
            for (int mf = 0; mf < 2; mf++)
                #pragma unroll
                for (int nf = 0; nf < 8; nf++)
                    mma_tf32(acc[mf][nf], af[mf], bf[nf]);
        }
        __syncthreads();
    }
    #pragma unroll
    for (int mf = 0; mf < 2; mf++) {
        int r0 = m0 + wm * 32 + mf * 16 + g;
        #pragma unroll
        for (int nf = 0; nf < 8; nf++) {
            int c0 = n0 + wn * 64 + nf * 8 + t4 * 2;
            float bb0 = bias ? bias[c0] : 0.f;
            float bb1 = bias ? bias[c0 + 1] : 0.f;
            float v0 = acc[mf][nf][0] + bb0, v1 = acc[mf][nf][1] + bb1;
            float v2 = acc[mf][nf][2] + bb0, v3 = acc[mf][nf][3] + bb1;
            if (relu) {
                v0 = fmaxf(v0, 0.f); v1 = fmaxf(v1, 0.f);
                v2 = fmaxf(v2, 0.f); v3 = fmaxf(v3, 0.f);
            }
            *(float2*)&C[(size_t)r0 * N + c0]       = make_float2(v0, v1);
            *(float2*)&C[(size_t)(r0 + 8) * N + c0] = make_float2(v2, v3);
        }
    }
}

// scores[bh,q,k] = (q.k)/8 + mask
__global__ void __launch_bounds__(256) attn_scores_kernel(const int* __restrict__ tokens) {
    int bh = blockIdx.x;
    int b = bh >> 1, h = bh & 1;
    int q0 = blockIdx.y * 32, k0 = blockIdx.z * 128;
    __shared__ float Qs[64][32];
    __shared__ float Ks[64][128];
    int tid = threadIdx.x;
    {
        int r = tid & 31, ds = (tid >> 5) * 8;
        const float* src = g_q + ((size_t)(b * LSEQ + q0 + r)) * D + h * DH + ds;
        #pragma unroll
        for (int i = 0; i < 8; i++) Qs[ds + i][r] = src[i];
    }
    {
        int r = tid >> 1, ds = (tid & 1) * 32;
        const float* src = g_k + ((size_t)(b * LSEQ + k0 + r)) * D + h * DH + ds;
        #pragma unroll
        for (int i = 0; i < 32; i++) Ks[ds + i][r] = src[i];
    }
    __syncthreads();
    int w = tid >> 5, lane = tid & 31;
    float acc[4][4];
    #pragma unroll
    for (int i = 0; i < 4; i++)
        #pragma unroll
        for (int j = 0; j < 4; j++) acc[i][j] = 0.f;
    #pragma unroll 4
    for (int d = 0; d < 64; d++) {
        float4 qv = *(const float4*)&Qs[d][w * 4];
        float4 kv = *(const float4*)&Ks[d][lane * 4];
        float qa[4] = {qv.x, qv.y, qv.z, qv.w};
        float ka[4] = {kv.x, kv.y, kv.z, kv.w};
        #pragma unroll
        for (int i = 0; i < 4; i++)
            #pragma unroll
            for (int j = 0; j < 4; j++) acc[i][j] = fmaf(qa[i], ka[j], acc[i][j]);
    }
    float mbias[4];
    #pragma unroll
    for (int j = 0; j < 4; j++)
        mbias[j] = (tokens[b * LSEQ + k0 + lane * 4 + j] != 0) ? 0.f : NEGV;
    #pragma unroll
    for (int i = 0; i < 4; i++) {
        int ql = q0 + w * 4 + i;
        float4 o = make_float4(acc[i][0] * 0.125f + mbias[0], acc[i][1] * 0.125f + mbias[1],
                               acc[i][2] * 0.125f + mbias[2], acc[i][3] * 0.125f + mbias[3]);
        *(float4*)&g_sc[((size_t)(bh * LSEQ + ql)) * LSEQ + k0 + lane * 4] = o;
    }
}

__global__ void __launch_bounds__(128) softmax_kernel() {
    int row = blockIdx.x * 4 + (threadIdx.x >> 5);
    int lane = threadIdx.x & 31;
    float* p = g_sc + (size_t)row * LSEQ;
    float v[8];
    float m = -INFINITY;
    #pragma unroll
    for (int i = 0; i < 8; i++) { v[i] = p[lane + 32 * i]; m = fmaxf(m, v[i]); }
    m = warp_max(m);
    float s = 0.f;
    #pragma unroll
    for (int i = 0; i < 8; i++) { v[i] = expf(v[i] - m); s += v[i]; }
    s = warp_sum(s);
    float inv = 1.f / s;
    #pragma unroll
    for (int i = 0; i < 8; i++) p[lane + 32 * i] = v[i] * inv;
}

__global__ void __launch_bounds__(256) attn_av_kernel() {
    int bh = blockIdx.x;
    int b = bh >> 1, h = bh & 1;
    int l0 = blockIdx.y * 64;
    __shared__ float Ast[64][68];
    __shared__ float Vs[64][64];
    int tid = threadIdx.x;
    int ty = tid >> 4, tx = tid & 15;
    float acc[4][4];
    #pragma unroll
    for (int i = 0; i < 4; i++)
        #pragma unroll
        for (int j = 0; j < 4; j++) acc[i][j] = 0.f;
    int lr = tid >> 2, lc = (tid & 3) * 16;
    for (int kc = 0; kc < 4; kc++) {
        const float* ap = g_sc + ((size_t)(bh * LSEQ + l0 + lr)) * LSEQ + kc * 64 + lc;
        #pragma unroll
        for (int u = 0; u < 4; u++) {
            float4 t = *(const float4*)(ap + u * 4);
            Ast[lc + u * 4 + 0][lr] = t.x; Ast[lc + u * 4 + 1][lr] = t.y;
            Ast[lc + u * 4 + 2][lr] = t.z; Ast[lc + u * 4 + 3][lr] = t.w;
        }
        const float* vp = g_v + ((size_t)(b * LSEQ + kc * 64 + lr)) * D + h * DH + lc;
        #pragma unroll
        for (int u = 0; u < 4; u++)
            *(float4*)&Vs[lr][lc + u * 4] = *(const float4*)(vp + u * 4);
        __syncthreads();
        #pragma unroll 4
        for (int kl = 0; kl < 64; kl++) {
            float4 av = *(const float4*)&Ast[kl][ty * 4];
            float4 vv = *(const float4*)&Vs[kl][tx * 4];
            float aa[4] = {av.x, av.y, av.z, av.w};
            float bb[4] = {vv.x, vv.y, vv.z, vv.w};
            #pragma unroll
            for (int i = 0; i < 4; i++)
                #pragma unroll
                for (int j = 0; j < 4; j++) acc[i][j] = fmaf(aa[i], bb[j], acc[i][j]);
        }
        __syncthreads();
    }
    #pragma unroll
    for (int i = 0; i < 4; i++) {
        float4 ov = make_float4(acc[i][0], acc[i][1], acc[i][2], acc[i][3]);
        *(float4*)&g_ao[((size_t)(b * LSEQ + l0 + ty * 4 + i)) * D + h * DH + tx * 4] = ov;
    }
}

__global__ void __launch_bounds__(128) add_ln_kernel(const float* __restrict__ g,
                                                     const float* __restrict__ b) {
    int row = blockIdx.x, tid = threadIdx.x;
    int w = tid >> 5, lane = tid & 31;
    float v = g_x[(size_t)row * D + tid] + g_tmp[(size_t)row * D + tid];
    float s = warp_sum(v);
    float s2 = warp_sum(v * v);
    __shared__ float ws[4], ws2[4];
    if (lane == 0) { ws[w] = s; ws2[w] = s2; }
    __syncthreads();
    s = ws[0] + ws[1] + ws[2] + ws[3];
    s2 = ws2[0] + ws2[1] + ws2[2] + ws2[3];
    float m = s * (1.f / D);
    float var = s2 * (1.f / D) - m * m;
    float inv = rsqrtf(var + 1e-5f);
    g_x[(size_t)row * D + tid] = (v - m) * inv * g[tid] + b[tid];
}

// ---------------- pooling / gate / final ----------------
__global__ void __launch_bounds__(128) tok_pool_kernel(const int* __restrict__ tokens,
                                                       const float* __restrict__ vvec) {
    int b = blockIdx.x, tid = threadIdx.x;
    int w = tid >> 5, lane = tid & 31;
    __shared__ float s_s[LSEQ];
    __shared__ float red[4];
    for (int l = w; l < LSEQ; l += 4) {
        float val = 0.f;
        #pragma unroll
        for (int d = lane; d < D; d += 32)
            val += tanhf(g_ffn[((size_t)(b * LSEQ + l)) * D + d]) * vvec[d];
        val = warp_sum(val);
        if (lane == 0) s_s[l] = (tokens[b * LSEQ + l] != 0) ? val : NEGV;
    }
    __syncthreads();
    float m = fmaxf(s_s[tid], s_s[tid + 128]);
    m = warp_max(m);
    if (lane == 0) red[w] = m;
    __syncthreads();
    m = fmaxf(fmaxf(red[0], red[1]), fmaxf(red[2], red[3]));
    __syncthreads();
    float e0 = expf(s_s[tid] - m), e1 = expf(s_s[tid + 128] - m);
    float ssum = warp_sum(e0 + e1);
    if (lane == 0) red[w] = ssum;
    __syncthreads();
    ssum = red[0] + red[1] + red[2] + red[3];
    float inv = 1.f / ssum;
    __syncthreads();
    s_s[tid] = e0 * inv; s_s[tid + 128] = e1 * inv;
    __syncthreads();
    float acc = 0.f;
    for (int l = 0; l < LSEQ; l++)
        acc = fmaf(s_s[l], g_x[((size_t)(b * LSEQ + l)) * D + tid], acc);
    g_trep[b * D + tid] = acc;
}

__global__ void __launch_bounds__(128) ent_pool_kernel(const int* __restrict__ ctx,
                                                       const float* __restrict__ Wa,
                                                       const float* __restrict__ ba,
                                                       const float* __restrict__ vvec) {
    int b = blockIdx.x, tid = threadIdx.x;
    int w = tid >> 5, lane = tid & 31;
    __shared__ float h_s[NCTX][D];
    __shared__ float s_s[NCTX];
    __shared__ int cs[NCTX];
    if (tid < NCTX) cs[tid] = ctx[b * NCTX + tid];
    __syncthreads();
    for (int j = 0; j < NCTX; j++)
        h_s[j][tid] = g_kg[(size_t)cs[j] * D + tid];
    __syncthreads();
    for (int j = w; j < NCTX; j += 4) {
        float val = 0.f;
        for (int d = lane; d < D; d += 32) {
            float acc = ba[d];
            #pragma unroll 8
            for (int kk = 0; kk < D; kk++)
                acc = fmaf(h_s[j][kk], Wa[kk * D + d], acc);
            val += tanhf(acc) * vvec[d];
        }
        val = warp_sum(val);
        if (lane == 0) s_s[j] = (cs[j] != 0) ? val : NEGV;
    }
    __syncthreads();
    if (w == 0) {
        float sv = s_s[lane];
        float m = warp_max(sv);
        float e = expf(sv - m);
        float ssum = warp_sum(e);
        s_s[lane] = e / ssum;
    }
    __syncthreads();
    float acc = 0.f;
    #pragma unroll
    for (int j = 0; j < NCTX; j++) acc = fmaf(s_s[j], h_s[j][tid], acc);
    g_erep[b * D + tid] = acc;
}

__global__ void __launch_bounds__(128) gate_kernel(const float* __restrict__ Wg,
                                                   const float* __restrict__ bg) {
    int b = blockIdx.x, tid = threadIdx.x;
    __shared__ float cat[2 * D];
    cat[tid] = g_trep[b * D + tid];
    cat[D + tid] = g_erep[b * D + tid];
    __syncthreads();
    float acc = bg[tid];
    #pragma unroll 8
    for (int j = 0; j < 2 * D; j++) acc = fmaf(cat[j], Wg[j * D + tid], acc);
    float sg = 1.f / (1.f + expf(-acc));
    g_user[b * D + tid] = sg * cat[tid] + (1.f - sg) * cat[D + tid];
}

__global__ void __launch_bounds__(256) final_kernel(float* __restrict__ out) {
    __shared__ float kg_s[128][17];
    __shared__ float user_t[D][BATCH];
    int n0 = blockIdx.x * 128, tid = threadIdx.x;
    for (int i = tid; i < D * BATCH; i += 256) {
        int d = i >> 6, bb = i & 63;
        user_t[d][bb] = g_user[bb * D + d];
    }
    int tn = tid >> 3, tb = tid & 7;
    float acc[4][8];
    #pragma unroll
    for (int i = 0; i < 4; i++)
        #pragma unroll
        for (int j = 0; j < 8; j++) acc[i][j] = 0.f;
    for (int dc = 0; dc < D; dc += 16) {
        __syncthreads();
        for (int i = tid; i < 128 * 16; i += 256) {
            int nl = i >> 4, dd = i & 15;
            int n = n0 + nl;
            kg_s[nl][dd] = (n < NE) ? g_kg[(size_t)n * D + dc + dd] : 0.f;
        }
        __syncthreads();
        #pragma unroll
        for (int dd = 0; dd < 16; dd++) {
            float kv[4], uv[8];
            #pragma unroll
            for (int i = 0; i < 4; i++) kv[i] = kg_s[tn * 4 + i][dd];
            #pragma unroll
            for (int j = 0; j < 8; j++) uv[j] = user_t[dc + dd][tb * 8 + j];
            #pragma unroll
            for (int i = 0; i < 4; i++)
                #pragma unroll
                for (int j = 0; j < 8; j++) acc[i][j] = fmaf(kv[i], uv[j], acc[i][j]);
        }
    }
    #pragma unroll
    for (int i = 0; i < 4; i++) {
        int n = n0 + tn * 4 + i;
        if (n < NE) {
            #pragma unroll
            for (int j = 0; j < 8; j++)
                out[(size_t)(tb * 8 + j) * NE + n] = acc[i][j];
        }
    }
}

// ---------------- launch ----------------
extern "C" void kernel_launch(void* const* d_in, const int* in_sizes, int n_in,
                              void* d_out, int out_size) {
    const int*   edge_idx = (const int*)d_in[0];
    const int*   edge_type = (const int*)d_in[1];
    const int*   ctx_ent  = (const int*)d_in[2];
    const int*   ctx_tok  = (const int*)d_in[3];
    const float* basis    = (const float*)d_in[4];
    const float* comp     = (const float*)d_in[5];
    const float* root     = (const float*)d_in[6];
    const float* rgcn_b   = (const float*)d_in[7];
    const float* tok_emb  = (const float*)d_in[8];
    const float* pos_emb  = (const float*)d_in[9];
    const float* Wqkv     = (const float*)d_in[10];
    const float* Wo       = (const float*)d_in[11];
    const float* ln1_g    = (const float*)d_in[12];
    const float* ln1_b    = (const float*)d_in[13];
    const float* ln2_g    = (const float*)d_in[14];
    const float* ln2_b    = (const float*)d_in[15];
    const float* W1       = (const float*)d_in[16];
    const float* b1       = (const float*)d_in[17];
    const float* W2       = (const float*)d_in[18];
    const float* b2       = (const float*)d_in[19];
    const float* ent_Wa   = (const float*)d_in[20];
    const float* ent_ba   = (const float*)d_in[21];
    const float* ent_v    = (const float*)d_in[22];
    const float* tok_Wa   = (const float*)d_in[23];
    const float* tok_ba   = (const float*)d_in[24];
    const float* tok_v    = (const float*)d_in[25];
    const float* Wg       = (const float*)d_in[26];
    const float* bg       = (const float*)d_in[27];
    float* out = (float*)d_out;

    init_ptrs_kernel<<<1, 1>>>();

    // --- RGCN ---
    zero_cnt_kernel<<<(NE * NREL + 255) / 256, 256>>>();
    rgcn_w_kernel<<<NE, 128>>>(basis, comp, root, rgcn_b);
    count_kernel<<<(NEDGE + 255) / 256, 256>>>(edge_idx, edge_type);
    scatter_kernel<<<NEDGE / 8, 256>>>(edge_idx, edge_type);

    // --- encoder ---
    embed_kernel<<<(BATCH * LSEQ * D) / 256, 256>>>(ctx_tok, tok_emb, pos_emb);
    const int M = BATCH * LSEQ;  // 16384
    for (int l = 0; l < NLAY; l++) {
        gemm_tc_kernel<<<dim3(M / 128, 1), 256>>>(Wqkv + (size_t)(l * 3 + 0) * D * D, nullptr, BUF_X, BUF_Q, M, D, D, 0);
        gemm_tc_kernel<<<dim3(M / 128, 1), 256>>>(Wqkv + (size_t)(l * 3 + 1) * D * D, nullptr, BUF_X, BUF_K, M, D, D, 0);
        gemm_tc_kernel<<<dim3(M / 128, 1), 256>>>(Wqkv + (size_t)(l * 3 + 2) * D * D, nullptr, BUF_X, BUF_V, M, D, D, 0);
        attn_scores_kernel<<<dim3(BATCH * NHEAD, LSEQ / 32, LSEQ / 128), 256>>>(ctx_tok);
        softmax_kernel<<<(BATCH * NHEAD * LSEQ) / 4, 128>>>();
        attn_av_kernel<<<dim3(BATCH * NHEAD, LSEQ / 64), 256>>>();
        gemm_tc_kernel<<<dim3(M / 128, 1), 256>>>(Wo + (size_t)l * D * D, nullptr, BUF_AO, BUF_TMP, M, D, D, 0);
        add_ln_kernel<<<M, 128>>>(ln1_g + l * D, ln1_b + l * D);
        gemm_tc_kernel<<<dim3(M / 128, FFND / 128), 256>>>(W1 + (size_t)l * D * FFND, b1 + l * FFND, BUF_X, BUF_FFN, M, FFND, D, 1);
        gemm_tc_kernel<<<dim3(M / 128, 1), 256>>>(W2 + (size_t)l * FFND * D, b2 + l * D, BUF_FFN, BUF_TMP, M, D, FFND, 0);
        add_ln_kernel<<<M, 128>>>(ln2_g + l * D, ln2_b + l * D);
    }

    // --- pooling / gate / score ---
    gemm_tc_kernel<<<dim3(M / 128, 1), 256>>>(tok_Wa, tok_ba, BUF_X, BUF_FFN, M, D, D, 0);
    tok_pool_kernel<<<BATCH, 128>>>(ctx_tok, tok_v);
    ent_pool_kernel<<<BATCH, 128>>>(ctx_ent, ent_Wa, ent_ba, ent_v);
    gate_kernel<<<BATCH, 128>>>(Wg, bg);
    final_kernel<<<(NE + 127) / 128, 256>>>(out);
}

// round 6
// speedup vs baseline: 1.2298x; 1.0740x over previous
#include <cuda_runtime.h>
#include <cuda_bf16.h>
#include <math.h>

#define NE      30000
#define NREL    18
#define NB      8
#define D       128
#define NEDGE   1000000
#define BATCH   64
#define LSEQ    256
#define NCTX    32
#define NHEAD   2
#define DH      64
#define FFND    512
#define NLAY    2
#define NEGV    (-1e9f)

// ---------------- device scratch (static, referenced ONLY in device code) ---
static __device__ float g_W[(size_t)NREL * NE * D];     // 276 MB
static __device__ float g_kg[(size_t)NE * D];
static __device__ int   g_cnt[NE * NREL];
static __device__ float g_x [BATCH * LSEQ * D];
static __device__ float g_q [BATCH * LSEQ * D];
static __device__ float g_k [BATCH * LSEQ * D];
static __device__ float g_v [BATCH * LSEQ * D];
static __device__ float g_sc[(size_t)BATCH * NHEAD * LSEQ * LSEQ]; // 33.5MB
static __device__ float g_ao[BATCH * LSEQ * D];
static __device__ float g_tmp[BATCH * LSEQ * D];
static __device__ float g_ffn[BATCH * LSEQ * FFND];
static __device__ float g_trep[BATCH * D];
static __device__ float g_erep[BATCH * D];
static __device__ float g_user[BATCH * D];
static __device__ float* g_bufs[8];

#define BUF_X   0
#define BUF_Q   1
#define BUF_K   2
#define BUF_V   3
#define BUF_AO  4
#define BUF_TMP 5
#define BUF_FFN 6

__global__ void init_ptrs_kernel() {
    g_bufs[BUF_X] = g_x;  g_bufs[BUF_Q] = g_q;  g_bufs[BUF_K] = g_k;
    g_bufs[BUF_V] = g_v;  g_bufs[BUF_AO] = g_ao; g_bufs[BUF_TMP] = g_tmp;
    g_bufs[BUF_FFN] = g_ffn;
}

// ---------------- helpers ----------------
__device__ __forceinline__ float warp_sum(float v) {
    #pragma unroll
    for (int o = 16; o > 0; o >>= 1) v += __shfl_xor_sync(0xFFFFFFFFu, v, o);
    return v;
}
__device__ __forceinline__ float warp_max(float v) {
    #pragma unroll
    for (int o = 16; o > 0; o >>= 1) v = fmaxf(v, __shfl_xor_sync(0xFFFFFFFFu, v, o));
    return v;
}
__device__ __forceinline__ void mma_tf32(float* c, const unsigned* a, const unsigned* b) {
    asm volatile(
        "mma.sync.aligned.m16n8k8.row.col.f32.tf32.tf32.f32 "
        "{%0,%1,%2,%3}, {%4,%5,%6,%7}, {%8,%9}, {%0,%1,%2,%3};\n"
        : "+f"(c[0]), "+f"(c[1]), "+f"(c[2]), "+f"(c[3])
        : "r"(a[0]), "r"(a[1]), "r"(a[2]), "r"(a[3]), "r"(b[0]), "r"(b[1]));
}
__device__ __forceinline__ unsigned f2tf(float x) {
    unsigned r;
    asm("cvt.rna.tf32.f32 %0, %1;" : "=r"(r) : "f"(x));
    return r;
}
// split x into tf32 hi + tf32 lo  (3xTF32 compensation)
__device__ __forceinline__ void tf_split(float x, unsigned& hi, unsigned& lo) {
    hi = f2tf(x);
    lo = f2tf(__fsub_rn(x, __uint_as_float(hi)));
}

// ---------------- RGCN ----------------
__global__ void __launch_bounds__(256) zero_cnt_kernel() {
    int i = blockIdx.x * blockDim.x + threadIdx.x;
    if (i < NE * NREL) g_cnt[i] = 0;
}

__global__ void __launch_bounds__(128) rgcn_w_kernel(const float* __restrict__ basis,
                                                     const float* __restrict__ comp,
                                                     const float* __restrict__ root,
                                                     const float* __restrict__ bias) {
    int n = blockIdx.x, d = threadIdx.x;
    __shared__ float sc[NREL * NB];
    for (int i = d; i < NREL * NB; i += 128) sc[i] = comp[i];
    __syncthreads();
    float bb[NB];
    #pragma unroll
    for (int q = 0; q < NB; q++) bb[q] = basis[((size_t)q * NE + n) * D + d];
    #pragma unroll
    for (int r = 0; r < NREL; r++) {
        float a = 0.f;
        #pragma unroll
        for (int q = 0; q < NB; q++) a = fmaf(sc[r * NB + q], bb[q], a);
        g_W[((size_t)r * NE + n) * D + d] = a;
    }
    g_kg[(size_t)n * D + d] = root[(size_t)n * D + d] + bias[d];
}

__global__ void __launch_bounds__(256) count_kernel(const int* __restrict__ ei,
                                                    const int* __restrict__ et) {
    int e = blockIdx.x * blockDim.x + threadIdx.x;
    if (e < NEDGE) atomicAdd(&g_cnt[ei[NEDGE + e] * NREL + et[e]], 1);
}

__global__ void __launch_bounds__(256) scatter_kernel(const int* __restrict__ ei,
                                                      const int* __restrict__ et) {
    int w = (blockIdx.x * blockDim.x + threadIdx.x) >> 5;
    int lane = threadIdx.x & 31;
    if (w >= NEDGE) return;
    int src = ei[w], dst = ei[NEDGE + w], r = et[w];
    float norm = 1.f / fmaxf((float)g_cnt[dst * NREL + r], 1.f);
    const float4* wr = (const float4*)(g_W + ((size_t)r * NE + src) * D);
    float4 v = wr[lane];
    float* o = g_kg + (size_t)dst * D + lane * 4;
    asm volatile("red.global.add.v4.f32 [%0], {%1,%2,%3,%4};"
                 :: "l"(o), "f"(v.x * norm), "f"(v.y * norm), "f"(v.z * norm), "f"(v.w * norm)
                 : "memory");
}

// ---------------- encoder ----------------
__global__ void __launch_bounds__(256) embed_kernel(const int* __restrict__ tokens,
                                                    const float* __restrict__ tok_emb,
                                                    const float* __restrict__ pos_emb) {
    int i = blockIdx.x * blockDim.x + threadIdx.x;
    int d = i & (D - 1);
    int bl = i >> 7;
    int l = bl & (LSEQ - 1);
    int tk = tokens[bl];
    g_x[i] = tok_emb[(size_t)tk * D + d] * 11.3137084989847603904f + pos_emb[l * D + d];
}

// ---- 3xTF32 tensor-core GEMM: C[M,N] = act(A@B + bias) ----
// 128x128 tile, BK=16, 8 warps (4x2), warp tile 32x64.
// qkv_mode: blockIdx.y selects weight slice Bw + y*D*D and output buffer csel+y.
__global__ void __launch_bounds__(256) gemm_tc_kernel(const float* __restrict__ Bw,
                                                      const float* __restrict__ bias,
                                                      int asel, int csel,
                                                      int M, int N, int K, int relu,
                                                      int qkv_mode) {
    int n0;
    if (qkv_mode) { Bw += (size_t)blockIdx.y * D * D; csel += blockIdx.y; n0 = 0; }
    else n0 = blockIdx.y * 128;
    const float* __restrict__ A = g_bufs[asel];
    float* __restrict__ C = g_bufs[csel];
    __shared__ float As[16][136];   // [k][m]
    __shared__ float Bs[16][136];   // [k][n]
    int m0 = blockIdx.x * 128;
    int tid = threadIdx.x;
    int wid = tid >> 5, lane = tid & 31;
    int wm = wid & 3, wn = wid >> 2;
    int g = lane >> 2, t4 = lane & 3;

    float acc[2][8][4];
    #pragma unroll
    for (int i = 0; i < 2; i++)
        #pragma unroll
        for (int j = 0; j < 8; j++)
            #pragma unroll
            for (int q = 0; q < 4; q++) acc[i][j][q] = 0.f;

    int ar = tid >> 1, ak = (tid & 1) * 8;
    int bk = tid >> 4, bn = (tid & 15) * 8;

    for (int kc = 0; kc < K; kc += 16) {
        const float* ap = A + (size_t)(m0 + ar) * K + kc + ak;
        float4 av0 = *(const float4*)ap;
        float4 av1 = *(const float4*)(ap + 4);
        As[ak + 0][ar] = av0.x; As[ak + 1][ar] = av0.y;
        As[ak + 2][ar] = av0.z; As[ak + 3][ar] = av0.w;
        As[ak + 4][ar] = av1.x; As[ak + 5][ar] = av1.y;
        As[ak + 6][ar] = av1.z; As[ak + 7][ar] = av1.w;
        const float* bp = Bw + (size_t)(kc + bk) * N + n0 + bn;
        *(float4*)&Bs[bk][bn]     = *(const float4*)bp;
        *(float4*)&Bs[bk][bn + 4] = *(const float4*)(bp + 4);
        __syncthreads();
        #pragma unroll
        for (int ks = 0; ks < 16; ks += 8) {
            unsigned ah[2][4], al[2][4];
            #pragma unroll
            for (int mf = 0; mf < 2; mf++) {
                int mm = wm * 32 + mf * 16;
                tf_split(As[ks + t4    ][mm + g    ], ah[mf][0], al[mf][0]);
                tf_split(As[ks + t4    ][mm + g + 8], ah[mf][1], al[mf][1]);
                tf_split(As[ks + t4 + 4][mm + g    ], ah[mf][2], al[mf][2]);
                tf_split(As[ks + t4 + 4][mm + g + 8], ah[mf][3], al[mf][3]);
            }
            #pragma unroll
            for (int nf = 0; nf < 8; nf++) {
                int nn = wn * 64 + nf * 8 + g;
                unsigned bh[2], bl[2];
                tf_split(Bs[ks + t4    ][nn], bh[0], bl[0]);
                tf_split(Bs[ks + t4 + 4][nn], bh[1], bl[1]);
                #pragma unroll
                for (int mf = 0; mf < 2; mf++) {
                    mma_tf32(acc[mf][nf], al[mf], bh);
                    mma_tf32(acc[mf][nf], ah[mf], bl);
                    mma_tf32(acc[mf][nf], ah[mf], bh);
                }
            }
        }
        __syncthreads();
    }
    #pragma unroll
    for (int mf = 0; mf < 2; mf++) {
        int r0 = m0 + wm * 32 + mf * 16 + g;
        #pragma unroll
        for (int nf = 0; nf < 8; nf++) {
            int c0 = n0 + wn * 64 + nf * 8 + t4 * 2;
            float bb0 = bias ? bias[c0] : 0.f;
            float bb1 = bias ? bias[c0 + 1] : 0.f;
            float v0 = acc[mf][nf][0] + bb0, v1 = acc[mf][nf][1] + bb1;
            float v2 = acc[mf][nf][2] + bb0, v3 = acc[mf][nf][3] + bb1;
            if (relu) {
                v0 = fmaxf(v0, 0.f); v1 = fmaxf(v1, 0.f);
                v2 = fmaxf(v2, 0.f); v3 = fmaxf(v3, 0.f);
            }
            *(float2*)&C[(size_t)r0 * N + c0]       = make_float2(v0, v1);
            *(float2*)&C[(size_t)(r0 + 8) * N + c0] = make_float2(v2, v3);
        }
    }
}

// ---- tensor-core attention scores (3xTF32): 64q x 64k tile, K=64 ----
// scores[bh,q,k] = (q.k)/8 + mask(k)
__global__ void __launch_bounds__(256) attn_scores_tc(const int* __restrict__ tokens) {
    int bh = blockIdx.x;
    int b = bh >> 1, h = bh & 1;
    int q0 = blockIdx.y * 64, k0 = blockIdx.z * 64;
    __shared__ float Qs[64][68];   // [q][d]
    __shared__ float Ks[64][68];   // [key][d]
    int tid = threadIdx.x;
    int r = tid >> 2, dg = (tid & 3) * 16;
    {
        const float* qp = g_q + (size_t)(b * LSEQ + q0 + r) * D + h * DH + dg;
        const float* kp = g_k + (size_t)(b * LSEQ + k0 + r) * D + h * DH + dg;
        #pragma unroll
        for (int u = 0; u < 4; u++) {
            *(float4*)&Qs[r][dg + u * 4] = *(const float4*)(qp + u * 4);
            *(float4*)&Ks[r][dg + u * 4] = *(const float4*)(kp + u * 4);
        }
    }
    __syncthreads();
    int wid = tid >> 5, lane = tid & 31;
    int wm = wid & 3, wn = wid >> 2;   // 4 q-warps x 2 key-warps
    int g = lane >> 2, t4 = lane & 3;
    int m0 = wm * 16;

    float acc[4][4];
    #pragma unroll
    for (int j = 0; j < 4; j++)
        #pragma unroll
        for (int q = 0; q < 4; q++) acc[j][q] = 0.f;

    #pragma unroll
    for (int ks = 0; ks < 64; ks += 8) {
        unsigned ah[4], al[4];
        tf_split(Qs[m0 + g    ][ks + t4    ], ah[0], al[0]);
        tf_split(Qs[m0 + g + 8][ks + t4    ], ah[1], al[1]);
        tf_split(Qs[m0 + g    ][ks + t4 + 4], ah[2], al[2]);
        tf_split(Qs[m0 + g + 8][ks + t4 + 4], ah[3], al[3]);
        #pragma unroll
        for (int nf = 0; nf < 4; nf++) {
            int nn = wn * 32 + nf * 8 + g;
            unsigned bh2[2], bl2[2];
            tf_split(Ks[nn][ks + t4    ], bh2[0], bl2[0]);
            tf_split(Ks[nn][ks + t4 + 4], bh2[1], bl2[1]);
            mma_tf32(acc[nf], al, bh2);
            mma_tf32(acc[nf], ah, bl2);
            mma_tf32(acc[nf], ah, bh2);
        }
    }
    int row0 = bh * LSEQ + q0 + m0 + g;
    #pragma unroll
    for (int nf = 0; nf < 4; nf++) {
        int c0 = k0 + wn * 32 + nf * 8 + t4 * 2;
        float mb0 = (tokens[b * LSEQ + c0] != 0) ? 0.f : NEGV;
        float mb1 = (tokens[b * LSEQ + c0 + 1] != 0) ? 0.f : NEGV;
        *(float2*)&g_sc[(size_t)row0 * LSEQ + c0] =
            make_float2(acc[nf][0] * 0.125f + mb0, acc[nf][1] * 0.125f + mb1);
        *(float2*)&g_sc[(size_t)(row0 + 8) * LSEQ + c0] =
            make_float2(acc[nf][2] * 0.125f + mb0, acc[nf][3] * 0.125f + mb1);
    }
}

__global__ void __launch_bounds__(128) softmax_kernel() {
    int row = blockIdx.x * 4 + (threadIdx.x >> 5);
    int lane = threadIdx.x & 31;
    float* p = g_sc + (size_t)row * LSEQ;
    float v[8];
    float m = -INFINITY;
    #pragma unroll
    for (int i = 0; i < 8; i++) { v[i] = p[lane + 32 * i]; m = fmaxf(m, v[i]); }
    m = warp_max(m);
    float s = 0.f;
    #pragma unroll
    for (int i = 0; i < 8; i++) { v[i] = expf(v[i] - m); s += v[i]; }
    s = warp_sum(s);
    float inv = 1.f / s;
    #pragma unroll
    for (int i = 0; i < 8; i++) p[lane + 32 * i] = v[i] * inv;
}

// ---- tensor-core AV (3xTF32): o[128l x 64d] = P[128l x 256k] @ V[256k x 64d] ----
__global__ void __launch_bounds__(256) attn_av_tc() {
    int bh = blockIdx.x;
    int b = bh >> 1, h = bh & 1;
    int l0 = blockIdx.y * 128;
    __shared__ float Ps[128][36];  // [l][k-chunk]
    __shared__ float Vs[32][68];   // [k][d]
    int tid = threadIdx.x;
    int wid = tid >> 5, lane = tid & 31;
    int wm = wid & 3, wn = wid >> 2;   // 4 l-warps x 2 d-warps
    int g = lane >> 2, t4 = lane & 3;

    float acc[2][4][4];
    #pragma unroll
    for (int i = 0; i < 2; i++)
        #pragma unroll
        for (int j = 0; j < 4; j++)
            #pragma unroll
            for (int q = 0; q < 4; q++) acc[i][j][q] = 0.f;

    int pr = tid >> 1, pk = (tid & 1) * 16;   // P fill: row pr, 16 k
    int vr = tid >> 3, vd = (tid & 7) * 8;    // V fill: row vr, 8 d

    for (int kc = 0; kc < 8; kc++) {
        const float* pp = g_sc + (size_t)(bh * LSEQ + l0 + pr) * LSEQ + kc * 32 + pk;
        #pragma unroll
        for (int u = 0; u < 4; u++)
            *(float4*)&Ps[pr][pk + u * 4] = *(const float4*)(pp + u * 4);
        const float* vp = g_v + (size_t)(b * LSEQ + kc * 32 + vr) * D + h * DH + vd;
        #pragma unroll
        for (int u = 0; u < 2; u++)
            *(float4*)&Vs[vr][vd + u * 4] = *(const float4*)(vp + u * 4);
        __syncthreads();
        #pragma unroll
        for (int ks = 0; ks < 32; ks += 8) {
            unsigned ah[2][4], al[2][4];
            #pragma unroll
            for (int mf = 0; mf < 2; mf++) {
                int mm = wm * 32 + mf * 16;
                tf_split(Ps[mm + g    ][ks + t4    ], ah[mf][0], al[mf][0]);
                tf_split(Ps[mm + g + 8][ks + t4    ], ah[mf][1], al[mf][1]);
                tf_split(Ps[mm + g    ][ks + t4 + 4], ah[mf][2], al[mf][2]);
                tf_split(Ps[mm + g + 8][ks + t4 + 4], ah[mf][3], al[mf][3]);
            }
            #pragma unroll
            for (int nf = 0; nf < 4; nf++) {
                int nn = wn * 32 + nf * 8 + g;
                unsigned bh2[2], bl2[2];
                tf_split(Vs[ks + t4    ][nn], bh2[0], bl2[0]);
                tf_split(Vs[ks + t4 + 4][nn], bh2[1], bl2[1]);
                #pragma unroll
                for (int mf = 0; mf < 2; mf++) {
                    mma_tf32(acc[mf][nf], al[mf], bh2);
                    mma_tf32(acc[mf][nf], ah[mf], bl2);
                    mma_tf32(acc[mf][nf], ah[mf], bh2);
                }
            }
        }
        __syncthreads();
    }
    #pragma unroll
    for (int mf = 0; mf < 2; mf++) {
        int r0 = b * LSEQ + l0 + wm * 32 + mf * 16 + g;
        #pragma unroll
        for (int nf = 0; nf < 4; nf++) {
            int c0 = h * DH + wn * 32 + nf * 8 + t4 * 2;
            *(float2*)&g_ao[(size_t)r0 * D + c0] = make_float2(acc[mf][nf][0], acc[mf][nf][1]);
            *(float2*)&g_ao[(size_t)(r0 + 8) * D + c0] = make_float2(acc[mf][nf][2], acc[mf][nf][3]);
        }
    }
}

__global__ void __launch_bounds__(128) add_ln_kernel(const float* __restrict__ g,
                                                     const float* __restrict__ b) {
    int row = blockIdx.x, tid = threadIdx.x;
    int w = tid >> 5, lane = tid & 31;
    float v = g_x[(size_t)row * D + tid] + g_tmp[(size_t)row * D + tid];
    float s = warp_sum(v);
    float s2 = warp_sum(v * v);
    __shared__ float ws[4], ws2[4];
    if (lane == 0) { ws[w] = s; ws2[w] = s2; }
    __syncthreads();
    s = ws[0] + ws[1] + ws[2] + ws[3];
    s2 = ws2[0] + ws2[1] + ws2[2] + ws2[3];
    float m = s * (1.f / D);
    float var = s2 * (1.f / D) - m * m;
    float inv = rsqrtf(var + 1e-5f);
    g_x[(size_t)row * D + tid] = (v - m) * inv * g[tid] + b[tid];
}

// ---------------- pooling / gate / final ----------------
__global__ void __launch_bounds__(128) tok_pool_kernel(const int* __restrict__ tokens,
                                                       const float* __restrict__ vvec) {
    int b = blockIdx.x, tid = threadIdx.x;
    int w = tid >> 5, lane = tid & 31;
    __shared__ float s_s[LSEQ];
    __shared__ float red[4];
    for (int l = w; l < LSEQ; l += 4) {
        float val = 0.f;
        #pragma unroll
        for (int d = lane; d < D; d += 32)
            val += tanhf(g_ffn[((size_t)(b * LSEQ + l)) * D + d]) * vvec[d];
        val = warp_sum(val);
        if (lane == 0) s_s[l] = (tokens[b * LSEQ + l] != 0) ? val : NEGV;
    }
    __syncthreads();
    float m = fmaxf(s_s[tid], s_s[tid + 128]);
    m = warp_max(m);
    if (lane == 0) red[w] = m;
    __syncthreads();
    m = fmaxf(fmaxf(red[0], red[1]), fmaxf(red[2], red[3]));
    __syncthreads();
    float e0 = expf(s_s[tid] - m), e1 = expf(s_s[tid + 128] - m);
    float ssum = warp_sum(e0 + e1);
    if (lane == 0) red[w] = ssum;
    __syncthreads();
    ssum = red[0] + red[1] + red[2] + red[3];
    float inv = 1.f / ssum;
    __syncthreads();
    s_s[tid] = e0 * inv; s_s[tid + 128] = e1 * inv;
    __syncthreads();
    float acc = 0.f;
    for (int l = 0; l < LSEQ; l++)
        acc = fmaf(s_s[l], g_x[((size_t)(b * LSEQ + l)) * D + tid], acc);
    g_trep[b * D + tid] = acc;
}

__global__ void __launch_bounds__(128) ent_pool_kernel(const int* __restrict__ ctx,
                                                       const float* __restrict__ Wa,
                                                       const float* __restrict__ ba,
                                                       const float* __restrict__ vvec) {
    int b = blockIdx.x, tid = threadIdx.x;
    int w = tid >> 5, lane = tid & 31;
    __shared__ float h_s[NCTX][D];
    __shared__ float s_s[NCTX];
    __shared__ int cs[NCTX];
    if (tid < NCTX) cs[tid] = ctx[b * NCTX + tid];
    __syncthreads();
    for (int j = 0; j < NCTX; j++)
        h_s[j][tid] = g_kg[(size_t)cs[j] * D + tid];
    __syncthreads();
    for (int j = w; j < NCTX; j += 4) {
        float val = 0.f;
        for (int d = lane; d < D; d += 32) {
            float acc = ba[d];
            #pragma unroll 8
            for (int kk = 0; kk < D; kk++)
                acc = fmaf(h_s[j][kk], Wa[kk * D + d], acc);
            val += tanhf(acc) * vvec[d];
        }
        val = warp_sum(val);
        if (lane == 0) s_s[j] = (cs[j] != 0) ? val : NEGV;
    }
    __syncthreads();
    if (w == 0) {
        float sv = s_s[lane];
        float m = warp_max(sv);
        float e = expf(sv - m);
        float ssum = warp_sum(e);
        s_s[lane] = e / ssum;
    }
    __syncthreads();
    float acc = 0.f;
    #pragma unroll
    for (int j = 0; j < NCTX; j++) acc = fmaf(s_s[j], h_s[j][tid], acc);
    g_erep[b * D + tid] = acc;
}

__global__ void __launch_bounds__(128) gate_kernel(const float* __restrict__ Wg,
                                                   const float* __restrict__ bg) {
    int b = blockIdx.x, tid = threadIdx.x;
    __shared__ float cat[2 * D];
    cat[tid] = g_trep[b * D + tid];
    cat[D + tid] = g_erep[b * D + tid];
    __syncthreads();
    float acc = bg[tid];
    #pragma unroll 8
    for (int j = 0; j < 2 * D; j++) acc = fmaf(cat[j], Wg[j * D + tid], acc);
    float sg = 1.f / (1.f + expf(-acc));
    g_user[b * D + tid] = sg * cat[tid] + (1.f - sg) * cat[D + tid];
}

__global__ void __launch_bounds__(256) final_kernel(float* __restrict__ out) {
    __shared__ float kg_s[128][17];
    __shared__ float user_t[D][BATCH];
    int n0 = blockIdx.x * 128, tid = threadIdx.x;
    for (int i = tid; i < D * BATCH; i += 256) {
        int d = i >> 6, bb = i & 63;
        user_t[d][bb] = g_user[bb * D + d];
    }
    int tn = tid >> 3, tb = tid & 7;
    float acc[4][8];
    #pragma unroll
    for (int i = 0; i < 4; i++)
        #pragma unroll
        for (int j = 0; j < 8; j++) acc[i][j] = 0.f;
    for (int dc = 0; dc < D; dc += 16) {
        __syncthreads();
        for (int i = tid; i < 128 * 16; i += 256) {
            int nl = i >> 4, dd = i & 15;
            int n = n0 + nl;
            kg_s[nl][dd] = (n < NE) ? g_kg[(size_t)n * D + dc + dd] : 0.f;
        }
        __syncthreads();
        #pragma unroll
        for (int dd = 0; dd < 16; dd++) {
            float kv[4], uv[8];
            #pragma unroll
            for (int i = 0; i < 4; i++) kv[i] = kg_s[tn * 4 + i][dd];
            #pragma unroll
            for (int j = 0; j < 8; j++) uv[j] = user_t[dc + dd][tb * 8 + j];
            #pragma unroll
            for (int i = 0; i < 4; i++)
                #pragma unroll
                for (int j = 0; j < 8; j++) acc[i][j] = fmaf(kv[i], uv[j], acc[i][j]);
        }
    }
    #pragma unroll
    for (int i = 0; i < 4; i++) {
        int n = n0 + tn * 4 + i;
        if (n < NE) {
            #pragma unroll
            for (int j = 0; j < 8; j++)
                out[(size_t)(tb * 8 + j) * NE + n] = acc[i][j];
        }
    }
}

// ---------------- launch ----------------
extern "C" void kernel_launch(void* const* d_in, const int* in_sizes, int n_in,
                              void* d_out, int out_size) {
    const int*   edge_idx = (const int*)d_in[0];
    const int*   edge_type = (const int*)d_in[1];
    const int*   ctx_ent  = (const int*)d_in[2];
    const int*   ctx_tok  = (const int*)d_in[3];
    const float* basis    = (const float*)d_in[4];
    const float* comp     = (const float*)d_in[5];
    const float* root     = (const float*)d_in[6];
    const float* rgcn_b   = (const float*)d_in[7];
    const float* tok_emb  = (const float*)d_in[8];
    const float* pos_emb  = (const float*)d_in[9];
    const float* Wqkv     = (const float*)d_in[10];
    const float* Wo       = (const float*)d_in[11];
    const float* ln1_g    = (const float*)d_in[12];
    const float* ln1_b    = (const float*)d_in[13];
    const float* ln2_g    = (const float*)d_in[14];
    const float* ln2_b    = (const float*)d_in[15];
    const float* W1       = (const float*)d_in[16];
    const float* b1       = (const float*)d_in[17];
    const float* W2       = (const float*)d_in[18];
    const float* b2       = (const float*)d_in[19];
    const float* ent_Wa   = (const float*)d_in[20];
    const float* ent_ba   = (const float*)d_in[21];
    const float* ent_v    = (const float*)d_in[22];
    const float* tok_Wa   = (const float*)d_in[23];
    const float* tok_ba   = (const float*)d_in[24];
    const float* tok_v    = (const float*)d_in[25];
    const float* Wg       = (const float*)d_in[26];
    const float* bg       = (const float*)d_in[27];
    float* out = (float*)d_out;

    init_ptrs_kernel<<<1, 1>>>();

    // --- RGCN ---
    zero_cnt_kernel<<<(NE * NREL + 255) / 256, 256>>>();
    rgcn_w_kernel<<<NE, 128>>>(basis, comp, root, rgcn_b);
    count_kernel<<<(NEDGE + 255) / 256, 256>>>(edge_idx, edge_type);
    scatter_kernel<<<NEDGE / 8, 256>>>(edge_idx, edge_type);

    // --- encoder ---
    embed_kernel<<<(BATCH * LSEQ * D) / 256, 256>>>(ctx_tok, tok_emb, pos_emb);
    const int M = BATCH * LSEQ;  // 16384
    for (int l = 0; l < NLAY; l++) {
        // fused QKV: grid.y=3 selects weight slice + output buffer (Q,K,V)
        gemm_tc_kernel<<<dim3(M / 128, 3), 256>>>(Wqkv + (size_t)l * 3 * D * D, nullptr, BUF_X, BUF_Q, M, D, D, 0, 1);
        attn_scores_tc<<<dim3(BATCH * NHEAD, LSEQ / 64, LSEQ / 64), 256>>>(ctx_tok);
        softmax_kernel<<<(BATCH * NHEAD * LSEQ) / 4, 128>>>();
        attn_av_tc<<<dim3(BATCH * NHEAD, LSEQ / 128), 256>>>();
        gemm_tc_kernel<<<dim3(M / 128, 1), 256>>>(Wo + (size_t)l * D * D, nullptr, BUF_AO, BUF_TMP, M, D, D, 0, 0);
        add_ln_kernel<<<M, 128>>>(ln1_g + l * D, ln1_b + l * D);
        gemm_tc_kernel<<<dim3(M / 128, FFND / 128), 256>>>(W1 + (size_t)l * D * FFND, b1 + l * FFND, BUF_X, BUF_FFN, M, FFND, D, 1, 0);
        gemm_tc_kernel<<<dim3(M / 128, 1), 256>>>(W2 + (size_t)l * FFND * D, b2 + l * D, BUF_FFN, BUF_TMP, M, D, FFND, 0, 0);
        add_ln_kernel<<<M, 128>>>(ln2_g + l * D, ln2_b + l * D);
    }

    // --- pooling / gate / score ---
    gemm_tc_kernel<<<dim3(M / 128, 1), 256>>>(tok_Wa, tok_ba, BUF_X, BUF_FFN, M, D, D, 0, 0);
    tok_pool_kernel<<<BATCH, 128>>>(ctx_tok, tok_v);
    ent_pool_kernel<<<BATCH, 128>>>(ctx_ent, ent_Wa, ent_ba, ent_v);
    gate_kernel<<<BATCH, 128>>>(Wg, bg);
    final_kernel<<<(NE + 127) / 128, 256>>>(out);
}

// round 7
// speedup vs baseline: 1.2555x; 1.0209x over previous
#include <cuda_runtime.h>
#include <cuda_bf16.h>
#include <math.h>

#define NE      30000
#define NREL    18
#define NB      8
#define D       128
#define NEDGE   1000000
#define BATCH   64
#define LSEQ    256
#define NCTX    32
#define NHEAD   2
#define DH      64
#define FFND    512
#define NLAY    2
#define NEGV    (-1e9f)

// ---------------- device scratch (static, referenced ONLY in device code) ---
static __device__ float g_W[(size_t)NREL * NE * D];     // 276 MB
static __device__ float g_kg[(size_t)NE * D];
static __device__ int   g_cnt[NE * NREL];
static __device__ int   g_deg[NE];
static __device__ int   g_off[NE + 1];
static __device__ int   g_cur[NE];
static __device__ int   g_elist[NEDGE];
static __device__ float g_x [BATCH * LSEQ * D];
static __device__ float g_q [BATCH * LSEQ * D];
static __device__ float g_k [BATCH * LSEQ * D];
static __device__ float g_v [BATCH * LSEQ * D];
static __device__ float g_sc[(size_t)BATCH * NHEAD * LSEQ * LSEQ]; // 33.5MB
static __device__ float g_ao[BATCH * LSEQ * D];
static __device__ float g_tmp[BATCH * LSEQ * D];
static __device__ float g_ffn[BATCH * LSEQ * FFND];
static __device__ float g_trep[BATCH * D];
static __device__ float g_erep[BATCH * D];
static __device__ float g_user[BATCH * D];
static __device__ float* g_bufs[8];

#define BUF_X   0
#define BUF_Q   1
#define BUF_K   2
#define BUF_V   3
#define BUF_AO  4
#define BUF_TMP 5
#define BUF_FFN 6

__global__ void init_ptrs_kernel() {
    g_bufs[BUF_X] = g_x;  g_bufs[BUF_Q] = g_q;  g_bufs[BUF_K] = g_k;
    g_bufs[BUF_V] = g_v;  g_bufs[BUF_AO] = g_ao; g_bufs[BUF_TMP] = g_tmp;
    g_bufs[BUF_FFN] = g_ffn;
}

// ---------------- helpers ----------------
__device__ __forceinline__ float warp_sum(float v) {
    #pragma unroll
    for (int o = 16; o > 0; o >>= 1) v += __shfl_xor_sync(0xFFFFFFFFu, v, o);
    return v;
}
__device__ __forceinline__ float warp_max(float v) {
    #pragma unroll
    for (int o = 16; o > 0; o >>= 1) v = fmaxf(v, __shfl_xor_sync(0xFFFFFFFFu, v, o));
    return v;
}
__device__ __forceinline__ void mma_tf32(float* c, const unsigned* a, const unsigned* b) {
    asm volatile(
        "mma.sync.aligned.m16n8k8.row.col.f32.tf32.tf32.f32 "
        "{%0,%1,%2,%3}, {%4,%5,%6,%7}, {%8,%9}, {%0,%1,%2,%3};\n"
        : "+f"(c[0]), "+f"(c[1]), "+f"(c[2]), "+f"(c[3])
        : "r"(a[0]), "r"(a[1]), "r"(a[2]), "r"(a[3]), "r"(b[0]), "r"(b[1]));
}
__device__ __forceinline__ unsigned f2tf(float x) {
    unsigned r;
    asm("cvt.rna.tf32.f32 %0, %1;" : "=r"(r) : "f"(x));
    return r;
}
__device__ __forceinline__ void tf_split(float x, unsigned& hi, unsigned& lo) {
    hi = f2tf(x);
    lo = f2tf(__fsub_rn(x, __uint_as_float(hi)));
}

// ---------------- RGCN ----------------
__global__ void __launch_bounds__(256) zero_cnt_kernel() {
    int i = blockIdx.x * blockDim.x + threadIdx.x;
    if (i < NE * NREL) g_cnt[i] = 0;
    if (i < NE) g_deg[i] = 0;
}

__global__ void __launch_bounds__(128) rgcn_w_kernel(const float* __restrict__ basis,
                                                     const float* __restrict__ comp,
                                                     const float* __restrict__ root,
                                                     const float* __restrict__ bias) {
    int n = blockIdx.x, d = threadIdx.x;
    __shared__ float sc[NREL * NB];
    for (int i = d; i < NREL * NB; i += 128) sc[i] = comp[i];
    __syncthreads();
    float bb[NB];
    #pragma unroll
    for (int q = 0; q < NB; q++) bb[q] = basis[((size_t)q * NE + n) * D + d];
    #pragma unroll
    for (int r = 0; r < NREL; r++) {
        float a = 0.f;
        #pragma unroll
        for (int q = 0; q < NB; q++) a = fmaf(sc[r * NB + q], bb[q], a);
        g_W[((size_t)r * NE + n) * D + d] = a;
    }
    g_kg[(size_t)n * D + d] = root[(size_t)n * D + d] + bias[d];
}

__global__ void __launch_bounds__(256) count_kernel(const int* __restrict__ ei,
                                                    const int* __restrict__ et) {
    int e = blockIdx.x * blockDim.x + threadIdx.x;
    if (e < NEDGE) {
        int dst = ei[NEDGE + e];
        atomicAdd(&g_cnt[dst * NREL + et[e]], 1);
        atomicAdd(&g_deg[dst], 1);
    }
}

// exclusive prefix sum over g_deg (single block, sequential chunks)
__global__ void __launch_bounds__(1024) scan_kernel() {
    __shared__ int warp_sums[32];
    __shared__ int carry_s;
    int tid = threadIdx.x, lane = tid & 31, w = tid >> 5;
    if (tid == 0) carry_s = 0;
    __syncthreads();
    for (int base = 0; base < NE; base += 1024) {
        int i = base + tid;
        int v = (i < NE) ? g_deg[i] : 0;
        int x = v;
        #pragma unroll
        for (int o = 1; o < 32; o <<= 1) {
            int y = __shfl_up_sync(0xFFFFFFFFu, x, o);
            if (lane >= o) x += y;
        }
        if (lane == 31) warp_sums[w] = x;
        __syncthreads();
        if (w == 0) {
            int s = warp_sums[lane];
            #pragma unroll
            for (int o = 1; o < 32; o <<= 1) {
                int y = __shfl_up_sync(0xFFFFFFFFu, s, o);
                if (lane >= o) s += y;
            }
            warp_sums[lane] = s;
        }
        __syncthreads();
        int block_excl = (w > 0) ? warp_sums[w - 1] : 0;
        int excl = carry_s + block_excl + x - v;
        if (i < NE) { g_off[i] = excl; g_cur[i] = excl; }
        __syncthreads();
        if (tid == 0) carry_s += warp_sums[31];
        __syncthreads();
    }
    if (tid == 0) g_off[NE] = carry_s;
}

__global__ void __launch_bounds__(256) fill_kernel(const int* __restrict__ ei,
                                                   const int* __restrict__ et) {
    int e = blockIdx.x * blockDim.x + threadIdx.x;
    if (e >= NEDGE) return;
    int dst = ei[NEDGE + e];
    int pos = atomicAdd(&g_cur[dst], 1);
    g_elist[pos] = ei[e] | (et[e] << 16);
}

// one warp per dst: accumulate W rows of its edges (no atomics), add into kg
__global__ void __launch_bounds__(256) agg_kernel() {
    int gw = (blockIdx.x * blockDim.x + threadIdx.x) >> 5;
    int lane = threadIdx.x & 31;
    if (gw >= NE) return;
    int off = g_off[gw], end = g_off[gw + 1];
    float a0 = 0.f, a1 = 0.f, a2 = 0.f, a3 = 0.f;
    for (int b = off; b < end; b += 32) {
        int n = min(32, end - b);
        int pk = (b + lane < end) ? g_elist[b + lane] : 0;
        for (int j = 0; j < n; j++) {
            int p = __shfl_sync(0xFFFFFFFFu, pk, j);
            int src = p & 0xFFFF, r = p >> 16;
            float norm = 1.f / fmaxf((float)g_cnt[gw * NREL + r], 1.f);
            float4 v = *(const float4*)(g_W + ((size_t)r * NE + src) * D + lane * 4);
            a0 = fmaf(v.x, norm, a0);
            a1 = fmaf(v.y, norm, a1);
            a2 = fmaf(v.z, norm, a2);
            a3 = fmaf(v.w, norm, a3);
        }
    }
    float* o = g_kg + (size_t)gw * D + lane * 4;
    float4 cur = *(float4*)o;
    *(float4*)o = make_float4(cur.x + a0, cur.y + a1, cur.z + a2, cur.w + a3);
}

// ---------------- encoder ----------------
__global__ void __launch_bounds__(256) embed_kernel(const int* __restrict__ tokens,
                                                    const float* __restrict__ tok_emb,
                                                    const float* __restrict__ pos_emb) {
    int i = blockIdx.x * blockDim.x + threadIdx.x;
    int d = i & (D - 1);
    int bl = i >> 7;
    int l = bl & (LSEQ - 1);
    int tk = tokens[bl];
    g_x[i] = tok_emb[(size_t)tk * D + d] * 11.3137084989847603904f + pos_emb[l * D + d];
}

// ---- 3xTF32 tensor-core GEMM: C[M,N] = act(A@B + bias) ----
__global__ void __launch_bounds__(256) gemm_tc_kernel(const float* __restrict__ Bw,
                                                      const float* __restrict__ bias,
                                                      int asel, int csel,
                                                      int M, int N, int K, int relu,
                                                      int qkv_mode) {
    int n0;
    if (qkv_mode) { Bw += (size_t)blockIdx.y * D * D; csel += blockIdx.y; n0 = 0; }
    else n0 = blockIdx.y * 128;
    const float* __restrict__ A = g_bufs[asel];
    float* __restrict__ C = g_bufs[csel];
    __shared__ float As[16][136];
    __shared__ float Bs[16][136];
    int m0 = blockIdx.x * 128;
    int tid = threadIdx.x;
    int wid = tid >> 5, lane = tid & 31;
    int wm = wid & 3, wn = wid >> 2;
    int g = lane >> 2, t4 = lane & 3;

    float acc[2][8][4];
    #pragma unroll
    for (int i = 0; i < 2; i++)
        #pragma unroll
        for (int j = 0; j < 8; j++)
            #pragma unroll
            for (int q = 0; q < 4; q++) acc[i][j][q] = 0.f;

    int ar = tid >> 1, ak = (tid & 1) * 8;
    int bk = tid >> 4, bn = (tid & 15) * 8;

    for (int kc = 0; kc < K; kc += 16) {
        const float* ap = A + (size_t)(m0 + ar) * K + kc + ak;
        float4 av0 = *(const float4*)ap;
        float4 av1 = *(const float4*)(ap + 4);
        As[ak + 0][ar] = av0.x; As[ak + 1][ar] = av0.y;
        As[ak + 2][ar] = av0.z; As[ak + 3][ar] = av0.w;
        As[ak + 4][ar] = av1.x; As[ak + 5][ar] = av1.y;
        As[ak + 6][ar] = av1.z; As[ak + 7][ar] = av1.w;
        const float* bp = Bw + (size_t)(kc + bk) * N + n0 + bn;
        *(float4*)&Bs[bk][bn]     = *(const float4*)bp;
        *(float4*)&Bs[bk][bn + 4] = *(const float4*)(bp + 4);
        __syncthreads();
        #pragma unroll
        for (int ks = 0; ks < 16; ks += 8) {
            unsigned ah[2][4], al[2][4];
            #pragma unroll
            for (int mf = 0; mf < 2; mf++) {
                int mm = wm * 32 + mf * 16;
                tf_split(As[ks + t4    ][mm + g    ], ah[mf][0], al[mf][0]);
                tf_split(As[ks + t4    ][mm + g + 8], ah[mf][1], al[mf][1]);
                tf_split(As[ks + t4 + 4][mm + g    ], ah[mf][2], al[mf][2]);
                tf_split(As[ks + t4 + 4][mm + g + 8], ah[mf][3], al[mf][3]);
            }
            #pragma unroll
            for (int nf = 0; nf < 8; nf++) {
                int nn = wn * 64 + nf * 8 + g;
                unsigned bh[2], bl[2];
                tf_split(Bs[ks + t4    ][nn], bh[0], bl[0]);
                tf_split(Bs[ks + t4 + 4][nn], bh[1], bl[1]);
                #pragma unroll
                for (int mf = 0; mf < 2; mf++) {
                    mma_tf32(acc[mf][nf], al[mf], bh);
                    mma_tf32(acc[mf][nf], ah[mf], bl);
                    mma_tf32(acc[mf][nf], ah[mf], bh);
                }
            }
        }
        __syncthreads();
    }
    #pragma unroll
    for (int mf = 0; mf < 2; mf++) {
        int r0 = m0 + wm * 32 + mf * 16 + g;
        #pragma unroll
        for (int nf = 0; nf < 8; nf++) {
            int c0 = n0 + wn * 64 + nf * 8 + t4 * 2;
            float bb0 = bias ? bias[c0] : 0.f;
            float bb1 = bias ? bias[c0 + 1] : 0.f;
            float v0 = acc[mf][nf][0] + bb0, v1 = acc[mf][nf][1] + bb1;
            float v2 = acc[mf][nf][2] + bb0, v3 = acc[mf][nf][3] + bb1;
            if (relu) {
                v0 = fmaxf(v0, 0.f); v1 = fmaxf(v1, 0.f);
                v2 = fmaxf(v2, 0.f); v3 = fmaxf(v3, 0.f);
            }
            *(float2*)&C[(size_t)r0 * N + c0]       = make_float2(v0, v1);
            *(float2*)&C[(size_t)(r0 + 8) * N + c0] = make_float2(v2, v3);
        }
    }
}

// ---- tensor-core attention scores (3xTF32) ----
__global__ void __launch_bounds__(256) attn_scores_tc(const int* __restrict__ tokens) {
    int bh = blockIdx.x;
    int b = bh >> 1, h = bh & 1;
    int q0 = blockIdx.y * 64, k0 = blockIdx.z * 64;
    __shared__ float Qs[64][68];
    __shared__ float Ks[64][68];
    int tid = threadIdx.x;
    int r = tid >> 2, dg = (tid & 3) * 16;
    {
        const float* qp = g_q + (size_t)(b * LSEQ + q0 + r) * D + h * DH + dg;
        const float* kp = g_k + (size_t)(b * LSEQ + k0 + r) * D + h * DH + dg;
        #pragma unroll
        for (int u = 0; u < 4; u++) {
            *(float4*)&Qs[r][dg + u * 4] = *(const float4*)(qp + u * 4);
            *(float4*)&Ks[r][dg + u * 4] = *(const float4*)(kp + u * 4);
        }
    }
    __syncthreads();
    int wid = tid >> 5, lane = tid & 31;
    int wm = wid & 3, wn = wid >> 2;
    int g = lane >> 2, t4 = lane & 3;
    int m0 = wm * 16;

    float acc[4][4];
    #pragma unroll
    for (int j = 0; j < 4; j++)
        #pragma unroll
        for (int q = 0; q < 4; q++) acc[j][q] = 0.f;

    #pragma unroll
    for (int ks = 0; ks < 64; ks += 8) {
        unsigned ah[4], al[4];
        tf_split(Qs[m0 + g    ][ks + t4    ], ah[0], al[0]);
        tf_split(Qs[m0 + g + 8][ks + t4    ], ah[1], al[1]);
        tf_split(Qs[m0 + g    ][ks + t4 + 4], ah[2], al[2]);
        tf_split(Qs[m0 + g + 8][ks + t4 + 4], ah[3], al[3]);
        #pragma unroll
        for (int nf = 0; nf < 4; nf++) {
            int nn = wn * 32 + nf * 8 + g;
            unsigned bh2[2], bl2[2];
            tf_split(Ks[nn][ks + t4    ], bh2[0], bl2[0]);
            tf_split(Ks[nn][ks + t4 + 4], bh2[1], bl2[1]);
            mma_tf32(acc[nf], al, bh2);
            mma_tf32(acc[nf], ah, bl2);
            mma_tf32(acc[nf], ah, bh2);
        }
    }
    int row0 = bh * LSEQ + q0 + m0 + g;
    #pragma unroll
    for (int nf = 0; nf < 4; nf++) {
        int c0 = k0 + wn * 32 + nf * 8 + t4 * 2;
        float mb0 = (tokens[b * LSEQ + c0] != 0) ? 0.f : NEGV;
        float mb1 = (tokens[b * LSEQ + c0 + 1] != 0) ? 0.f : NEGV;
        *(float2*)&g_sc[(size_t)row0 * LSEQ + c0] =
            make_float2(acc[nf][0] * 0.125f + mb0, acc[nf][1] * 0.125f + mb1);
        *(float2*)&g_sc[(size_t)(row0 + 8) * LSEQ + c0] =
            make_float2(acc[nf][2] * 0.125f + mb0, acc[nf][3] * 0.125f + mb1);
    }
}

__global__ void __launch_bounds__(128) softmax_kernel() {
    int row = blockIdx.x * 4 + (threadIdx.x >> 5);
    int lane = threadIdx.x & 31;
    float* p = g_sc + (size_t)row * LSEQ;
    float v[8];
    float m = -INFINITY;
    #pragma unroll
    for (int i = 0; i < 8; i++) { v[i] = p[lane + 32 * i]; m = fmaxf(m, v[i]); }
    m = warp_max(m);
    float s = 0.f;
    #pragma unroll
    for (int i = 0; i < 8; i++) { v[i] = expf(v[i] - m); s += v[i]; }
    s = warp_sum(s);
    float inv = 1.f / s;
    #pragma unroll
    for (int i = 0; i < 8; i++) p[lane + 32 * i] = v[i] * inv;
}

// ---- tensor-core AV (3xTF32) ----
__global__ void __launch_bounds__(256) attn_av_tc() {
    int bh = blockIdx.x;
    int b = bh >> 1, h = bh & 1;
    int l0 = blockIdx.y * 128;
    __shared__ float Ps[128][36];
    __shared__ float Vs[32][68];
    int tid = threadIdx.x;
    int wid = tid >> 5, lane = tid & 31;
    int wm = wid & 3, wn = wid >> 2;
    int g = lane >> 2, t4 = lane & 3;

    float acc[2][4][4];
    #pragma unroll
    for (int i = 0; i < 2; i++)
        #pragma unroll
        for (int j = 0; j < 4; j++)
            #pragma unroll
            for (int q = 0; q < 4; q++) acc[i][j][q] = 0.f;

    int pr = tid >> 1, pk = (tid & 1) * 16;
    int vr = tid >> 3, vd = (tid & 7) * 8;

    for (int kc = 0; kc < 8; kc++) {
        const float* pp = g_sc + (size_t)(bh * LSEQ + l0 + pr) * LSEQ + kc * 32 + pk;
        #pragma unroll
        for (int u = 0; u < 4; u++)
            *(float4*)&Ps[pr][pk + u * 4] = *(const float4*)(pp + u * 4);
        const float* vp = g_v + (size_t)(b * LSEQ + kc * 32 + vr) * D + h * DH + vd;
        #pragma unroll
        for (int u = 0; u < 2; u++)
            *(float4*)&Vs[vr][vd + u * 4] = *(const float4*)(vp + u * 4);
        __syncthreads();
        #pragma unroll
        for (int ks = 0; ks < 32; ks += 8) {
            unsigned ah[2][4], al[2][4];
            #pragma unroll
            for (int mf = 0; mf < 2; mf++) {
                int mm = wm * 32 + mf * 16;
                tf_split(Ps[mm + g    ][ks + t4    ], ah[mf][0], al[mf][0]);
                tf_split(Ps[mm + g + 8][ks + t4    ], ah[mf][1], al[mf][1]);
                tf_split(Ps[mm + g    ][ks + t4 + 4], ah[mf][2], al[mf][2]);
                tf_split(Ps[mm + g + 8][ks + t4 + 4], ah[mf][3], al[mf][3]);
            }
            #pragma unroll
            for (int nf = 0; nf < 4; nf++) {
                int nn = wn * 32 + nf * 8 + g;
                unsigned bh2[2], bl2[2];
                tf_split(Vs[ks + t4    ][nn], bh2[0], bl2[0]);
                tf_split(Vs[ks + t4 + 4][nn], bh2[1], bl2[1]);
                #pragma unroll
                for (int mf = 0; mf < 2; mf++) {
                    mma_tf32(acc[mf][nf], al[mf], bh2);
                    mma_tf32(acc[mf][nf], ah[mf], bl2);
                    mma_tf32(acc[mf][nf], ah[mf], bh2);
                }
            }
        }
        __syncthreads();
    }
    #pragma unroll
    for (int mf = 0; mf < 2; mf++) {
        int r0 = b * LSEQ + l0 + wm * 32 + mf * 16 + g;
        #pragma unroll
        for (int nf = 0; nf < 4; nf++) {
            int c0 = h * DH + wn * 32 + nf * 8 + t4 * 2;
            *(float2*)&g_ao[(size_t)r0 * D + c0] = make_float2(acc[mf][nf][0], acc[mf][nf][1]);
            *(float2*)&g_ao[(size_t)(r0 + 8) * D + c0] = make_float2(acc[mf][nf][2], acc[mf][nf][3]);
        }
    }
}

__global__ void __launch_bounds__(128) add_ln_kernel(const float* __restrict__ g,
                                                     const float* __restrict__ b) {
    int row = blockIdx.x, tid = threadIdx.x;
    int w = tid >> 5, lane = tid & 31;
    float v = g_x[(size_t)row * D + tid] + g_tmp[(size_t)row * D + tid];
    float s = warp_sum(v);
    float s2 = warp_sum(v * v);
    __shared__ float ws[4], ws2[4];
    if (lane == 0) { ws[w] = s; ws2[w] = s2; }
    __syncthreads();
    s = ws[0] + ws[1] + ws[2] + ws[3];
    s2 = ws2[0] + ws2[1] + ws2[2] + ws2[3];
    float m = s * (1.f / D);
    float var = s2 * (1.f / D) - m * m;
    float inv = rsqrtf(var + 1e-5f);
    g_x[(size_t)row * D + tid] = (v - m) * inv * g[tid] + b[tid];
}

// ---------------- pooling / gate / final ----------------
__global__ void __launch_bounds__(128) tok_pool_kernel(const int* __restrict__ tokens,
                                                       const float* __restrict__ vvec) {
    int b = blockIdx.x, tid = threadIdx.x;
    int w = tid >> 5, lane = tid & 31;
    __shared__ float s_s[LSEQ];
    __shared__ float red[4];
    for (int l = w; l < LSEQ; l += 4) {
        float val = 0.f;
        #pragma unroll
        for (int d = lane; d < D; d += 32)
            val += tanhf(g_ffn[((size_t)(b * LSEQ + l)) * D + d]) * vvec[d];
        val = warp_sum(val);
        if (lane == 0) s_s[l] = (tokens[b * LSEQ + l] != 0) ? val : NEGV;
    }
    __syncthreads();
    float m = fmaxf(s_s[tid], s_s[tid + 128]);
    m = warp_max(m);
    if (lane == 0) red[w] = m;
    __syncthreads();
    m = fmaxf(fmaxf(red[0], red[1]), fmaxf(red[2], red[3]));
    __syncthreads();
    float e0 = expf(s_s[tid] - m), e1 = expf(s_s[tid + 128] - m);
    float ssum = warp_sum(e0 + e1);
    if (lane == 0) red[w] = ssum;
    __syncthreads();
    ssum = red[0] + red[1] + red[2] + red[3];
    float inv = 1.f / ssum;
    __syncthreads();
    s_s[tid] = e0 * inv; s_s[tid + 128] = e1 * inv;
    __syncthreads();
    float acc = 0.f;
    for (int l = 0; l < LSEQ; l++)
        acc = fmaf(s_s[l], g_x[((size_t)(b * LSEQ + l)) * D + tid], acc);
    g_trep[b * D + tid] = acc;
}

__global__ void __launch_bounds__(128) ent_pool_kernel(const int* __restrict__ ctx,
                                                       const float* __restrict__ Wa,
                                                       const float* __restrict__ ba,
                                                       const float* __restrict__ vvec) {
    int b = blockIdx.x, tid = threadIdx.x;
    int w = tid >> 5, lane = tid & 31;
    __shared__ float h_s[NCTX][D];
    __shared__ float s_s[NCTX];
    __shared__ int cs[NCTX];
    if (tid < NCTX) cs[tid] = ctx[b * NCTX + tid];
    __syncthreads();
    for (int j = 0; j < NCTX; j++)
        h_s[j][tid] = g_kg[(size_t)cs[j] * D + tid];
    __syncthreads();
    for (int j = w; j < NCTX; j += 4) {
        float val = 0.f;
        for (int d = lane; d < D; d += 32) {
            float acc = ba[d];
            #pragma unroll 8
            for (int kk = 0; kk < D; kk++)
                acc = fmaf(h_s[j][kk], Wa[kk * D + d], acc);
            val += tanhf(acc) * vvec[d];
        }
        val = warp_sum(val);
        if (lane == 0) s_s[j] = (cs[j] != 0) ? val : NEGV;
    }
    __syncthreads();
    if (w == 0) {
        float sv = s_s[lane];
        float m = warp_max(sv);
        float e = expf(sv - m);
        float ssum = warp_sum(e);
        s_s[lane] = e / ssum;
    }
    __syncthreads();
    float acc = 0.f;
    #pragma unroll
    for (int j = 0; j < NCTX; j++) acc = fmaf(s_s[j], h_s[j][tid], acc);
    g_erep[b * D + tid] = acc;
}

__global__ void __launch_bounds__(128) gate_kernel(const float* __restrict__ Wg,
                                                   const float* __restrict__ bg) {
    int b = blockIdx.x, tid = threadIdx.x;
    __shared__ float cat[2 * D];
    cat[tid] = g_trep[b * D + tid];
    cat[D + tid] = g_erep[b * D + tid];
    __syncthreads();
    float acc = bg[tid];
    #pragma unroll 8
    for (int j = 0; j < 2 * D; j++) acc = fmaf(cat[j], Wg[j * D + tid], acc);
    float sg = 1.f / (1.f + expf(-acc));
    g_user[b * D + tid] = sg * cat[tid] + (1.f - sg) * cat[D + tid];
}

__global__ void __launch_bounds__(256) final_kernel(float* __restrict__ out) {
    __shared__ float kg_s[128][17];
    __shared__ float user_t[D][BATCH];
    int n0 = blockIdx.x * 128, tid = threadIdx.x;
    for (int i = tid; i < D * BATCH; i += 256) {
        int d = i >> 6, bb = i & 63;
        user_t[d][bb] = g_user[bb * D + d];
    }
    int tn = tid >> 3, tb = tid & 7;
    float acc[4][8];
    #pragma unroll
    for (int i = 0; i < 4; i++)
        #pragma unroll
        for (int j = 0; j < 8; j++) acc[i][j] = 0.f;
    for (int dc = 0; dc < D; dc += 16) {
        __syncthreads();
        for (int i = tid; i < 128 * 16; i += 256) {
            int nl = i >> 4, dd = i & 15;
            int n = n0 + nl;
            kg_s[nl][dd] = (n < NE) ? g_kg[(size_t)n * D + dc + dd] : 0.f;
        }
        __syncthreads();
        #pragma unroll
        for (int dd = 0; dd < 16; dd++) {
            float kv[4], uv[8];
            #pragma unroll
            for (int i = 0; i < 4; i++) kv[i] = kg_s[tn * 4 + i][dd];
            #pragma unroll
            for (int j = 0; j < 8; j++) uv[j] = user_t[dc + dd][tb * 8 + j];
            #pragma unroll
            for (int i = 0; i < 4; i++)
                #pragma unroll
                for (int j = 0; j < 8; j++) acc[i][j] = fmaf(kv[i], uv[j], acc[i][j]);
        }
    }
    #pragma unroll
    for (int i = 0; i < 4; i++) {
        int n = n0 + tn * 4 + i;
        if (n < NE) {
            #pragma unroll
            for (int j = 0; j < 8; j++)
                out[(size_t)(tb * 8 + j) * NE + n] = acc[i][j];
        }
    }
}

// ---------------- launch ----------------
extern "C" void kernel_launch(void* const* d_in, const int* in_sizes, int n_in,
                              void* d_out, int out_size) {
    const int*   edge_idx = (const int*)d_in[0];
    const int*   edge_type = (const int*)d_in[1];
    const int*   ctx_ent  = (const int*)d_in[2];
    const int*   ctx_tok  = (const int*)d_in[3];
    const float* basis    = (const float*)d_in[4];
    const float* comp     = (const float*)d_in[5];
    const float* root     = (const float*)d_in[6];
    const float* rgcn_b   = (const float*)d_in[7];
    const float* tok_emb  = (const float*)d_in[8];
    const float* pos_emb  = (const float*)d_in[9];
    const float* Wqkv     = (const float*)d_in[10];
    const float* Wo       = (const float*)d_in[11];
    const float* ln1_g    = (const float*)d_in[12];
    const float* ln1_b    = (const float*)d_in[13];
    const float* ln2_g    = (const float*)d_in[14];
    const float* ln2_b    = (const float*)d_in[15];
    const float* W1       = (const float*)d_in[16];
    const float* b1       = (const float*)d_in[17];
    const float* W2       = (const float*)d_in[18];
    const float* b2       = (const float*)d_in[19];
    const float* ent_Wa   = (const float*)d_in[20];
    const float* ent_ba   = (const float*)d_in[21];
    const float* ent_v    = (const float*)d_in[22];
    const float* tok_Wa   = (const float*)d_in[23];
    const float* tok_ba   = (const float*)d_in[24];
    const float* tok_v    = (const float*)d_in[25];
    const float* Wg       = (const float*)d_in[26];
    const float* bg       = (const float*)d_in[27];
    float* out = (float*)d_out;

    init_ptrs_kernel<<<1, 1>>>();

    // --- RGCN (CSR, no atomics on kg) ---
    zero_cnt_kernel<<<(NE * NREL + 255) / 256, 256>>>();
    rgcn_w_kernel<<<NE, 128>>>(basis, comp, root, rgcn_b);
    count_kernel<<<(NEDGE + 255) / 256, 256>>>(edge_idx, edge_type);
    scan_kernel<<<1, 1024>>>();
    fill_kernel<<<(NEDGE + 255) / 256, 256>>>(edge_idx, edge_type);
    agg_kernel<<<(NE * 32 + 255) / 256, 256>>>();

    // --- encoder ---
    embed_kernel<<<(BATCH * LSEQ * D) / 256, 256>>>(ctx_tok, tok_emb, pos_emb);
    const int M = BATCH * LSEQ;  // 16384
    for (int l = 0; l < NLAY; l++) {
        gemm_tc_kernel<<<dim3(M / 128, 3), 256>>>(Wqkv + (size_t)l * 3 * D * D, nullptr, BUF_X, BUF_Q, M, D, D, 0, 1);
        attn_scores_tc<<<dim3(BATCH * NHEAD, LSEQ / 64, LSEQ / 64), 256>>>(ctx_tok);
        softmax_kernel<<<(BATCH * NHEAD * LSEQ) / 4, 128>>>();
        attn_av_tc<<<dim3(BATCH * NHEAD, LSEQ / 128), 256>>>();
        gemm_tc_kernel<<<dim3(M / 128, 1), 256>>>(Wo + (size_t)l * D * D, nullptr, BUF_AO, BUF_TMP, M, D, D, 0, 0);
        add_ln_kernel<<<M, 128>>>(ln1_g + l * D, ln1_b + l * D);
        gemm_tc_kernel<<<dim3(M / 128, FFND / 128), 256>>>(W1 + (size_t)l * D * FFND, b1 + l * FFND, BUF_X, BUF_FFN, M, FFND, D, 1, 0);
        gemm_tc_kernel<<<dim3(M / 128, 1), 256>>>(W2 + (size_t)l * FFND * D, b2 + l * D, BUF_FFN, BUF_TMP, M, D, FFND, 0, 0);
        add_ln_kernel<<<M, 128>>>(ln2_g + l * D, ln2_b + l * D);
    }

    // --- pooling / gate / score ---
    gemm_tc_kernel<<<dim3(M / 128, 1), 256>>>(tok_Wa, tok_ba, BUF_X, BUF_FFN, M, D, D, 0, 0);
    tok_pool_kernel<<<BATCH, 128>>>(ctx_tok, tok_v);
    ent_pool_kernel<<<BATCH, 128>>>(ctx_ent, ent_Wa, ent_ba, ent_v);
    gate_kernel<<<BATCH, 128>>>(Wg, bg);
    final_kernel<<<(NE + 127) / 128, 256>>>(out);
}

// round 8
// speedup vs baseline: 1.2671x; 1.0092x over previous
#include <cuda_runtime.h>
#include <cuda_bf16.h>
#include <math.h>

#define NE      30000
#define NREL    18
#define NB      8
#define D       128
#define NEDGE   1000000
#define BATCH   64
#define LSEQ    256
#define NCTX    32
#define NHEAD   2
#define DH      64
#define FFND    512
#define NLAY    2
#define NEGV    (-1e9f)

// ---------------- device scratch (static, referenced ONLY in device code) ---
static __device__ float g_W[(size_t)NREL * NE * D];     // 276 MB
static __device__ float g_kg[(size_t)NE * D];
static __device__ int   g_cnt[NE * NREL];
static __device__ int   g_off[NE + 1];
static __device__ int   g_cur[NE];
static __device__ int   g_elist[NEDGE];
static __device__ float g_x [BATCH * LSEQ * D];
static __device__ float g_q [BATCH * LSEQ * D];
static __device__ float g_k [BATCH * LSEQ * D];
static __device__ float g_v [BATCH * LSEQ * D];
static __device__ float g_sc[(size_t)BATCH * NHEAD * LSEQ * LSEQ]; // 33.5MB
static __device__ float g_ao[BATCH * LSEQ * D];
static __device__ float g_tmp[BATCH * LSEQ * D];
static __device__ float g_ffn[BATCH * LSEQ * FFND];
static __device__ float g_trep[BATCH * D];
static __device__ float g_erep[BATCH * D];
static __device__ float g_user[BATCH * D];
static __device__ float* g_bufs[8];

#define BUF_X   0
#define BUF_Q   1
#define BUF_K   2
#define BUF_V   3
#define BUF_AO  4
#define BUF_TMP 5
#define BUF_FFN 6

__global__ void init_ptrs_kernel() {
    g_bufs[BUF_X] = g_x;  g_bufs[BUF_Q] = g_q;  g_bufs[BUF_K] = g_k;
    g_bufs[BUF_V] = g_v;  g_bufs[BUF_AO] = g_ao; g_bufs[BUF_TMP] = g_tmp;
    g_bufs[BUF_FFN] = g_ffn;
}

// ---------------- helpers ----------------
__device__ __forceinline__ float warp_sum(float v) {
    #pragma unroll
    for (int o = 16; o > 0; o >>= 1) v += __shfl_xor_sync(0xFFFFFFFFu, v, o);
    return v;
}
__device__ __forceinline__ float warp_max(float v) {
    #pragma unroll
    for (int o = 16; o > 0; o >>= 1) v = fmaxf(v, __shfl_xor_sync(0xFFFFFFFFu, v, o));
    return v;
}
__device__ __forceinline__ void mma_tf32(float* c, const unsigned* a, const unsigned* b) {
    asm volatile(
        "mma.sync.aligned.m16n8k8.row.col.f32.tf32.tf32.f32 "
        "{%0,%1,%2,%3}, {%4,%5,%6,%7}, {%8,%9}, {%0,%1,%2,%3};\n"
        : "+f"(c[0]), "+f"(c[1]), "+f"(c[2]), "+f"(c[3])
        : "r"(a[0]), "r"(a[1]), "r"(a[2]), "r"(a[3]), "r"(b[0]), "r"(b[1]));
}
__device__ __forceinline__ unsigned f2tf(float x) {
    unsigned r;
    asm("cvt.rna.tf32.f32 %0, %1;" : "=r"(r) : "f"(x));
    return r;
}
__device__ __forceinline__ void tf_split(float x, unsigned& hi, unsigned& lo) {
    hi = f2tf(x);
    lo = f2tf(__fsub_rn(x, __uint_as_float(hi)));
}

// ---------------- RGCN ----------------
__global__ void __launch_bounds__(256) zero_cnt_kernel() {
    int i = blockIdx.x * blockDim.x + threadIdx.x;
    if (i < NE * NREL) g_cnt[i] = 0;
}

__global__ void __launch_bounds__(128) rgcn_w_kernel(const float* __restrict__ basis,
                                                     const float* __restrict__ comp,
                                                     const float* __restrict__ root,
                                                     const float* __restrict__ bias) {
    int n = blockIdx.x, d = threadIdx.x;
    __shared__ float sc[NREL * NB];
    for (int i = d; i < NREL * NB; i += 128) sc[i] = comp[i];
    __syncthreads();
    float bb[NB];
    #pragma unroll
    for (int q = 0; q < NB; q++) bb[q] = basis[((size_t)q * NE + n) * D + d];
    #pragma unroll
    for (int r = 0; r < NREL; r++) {
        float a = 0.f;
        #pragma unroll
        for (int q = 0; q < NB; q++) a = fmaf(sc[r * NB + q], bb[q], a);
        g_W[((size_t)r * NE + n) * D + d] = a;
    }
    g_kg[(size_t)n * D + d] = root[(size_t)n * D + d] + bias[d];
}

__global__ void __launch_bounds__(256) count_kernel(const int* __restrict__ ei,
                                                    const int* __restrict__ et) {
    int e = blockIdx.x * blockDim.x + threadIdx.x;
    if (e < NEDGE) {
        int dst = ei[NEDGE + e];
        atomicAdd(&g_cnt[dst * NREL + et[e]], 1);
    }
}

// exclusive prefix sum over per-dst degree (degree = sum of cnt row)
__global__ void __launch_bounds__(1024) scan_kernel() {
    __shared__ int warp_sums[32];
    __shared__ int carry_s;
    int tid = threadIdx.x, lane = tid & 31, w = tid >> 5;
    if (tid == 0) carry_s = 0;
    __syncthreads();
    for (int base = 0; base < NE; base += 1024) {
        int i = base + tid;
        int v = 0;
        if (i < NE) {
            #pragma unroll
            for (int r = 0; r < NREL; r++) v += g_cnt[i * NREL + r];
        }
        int x = v;
        #pragma unroll
        for (int o = 1; o < 32; o <<= 1) {
            int y = __shfl_up_sync(0xFFFFFFFFu, x, o);
            if (lane >= o) x += y;
        }
        if (lane == 31) warp_sums[w] = x;
        __syncthreads();
        if (w == 0) {
            int s = warp_sums[lane];
            #pragma unroll
            for (int o = 1; o < 32; o <<= 1) {
                int y = __shfl_up_sync(0xFFFFFFFFu, s, o);
                if (lane >= o) s += y;
            }
            warp_sums[lane] = s;
        }
        __syncthreads();
        int block_excl = (w > 0) ? warp_sums[w - 1] : 0;
        int excl = carry_s + block_excl + x - v;
        if (i < NE) { g_off[i] = excl; g_cur[i] = excl; }
        __syncthreads();
        if (tid == 0) carry_s += warp_sums[31];
        __syncthreads();
    }
    if (tid == 0) g_off[NE] = carry_s;
}

__global__ void __launch_bounds__(256) fill_kernel(const int* __restrict__ ei,
                                                   const int* __restrict__ et) {
    int e = blockIdx.x * blockDim.x + threadIdx.x;
    if (e >= NEDGE) return;
    int dst = ei[NEDGE + e];
    int pos = atomicAdd(&g_cur[dst], 1);
    g_elist[pos] = ei[e] | (et[e] << 16);
}

// one warp per dst: accumulate W rows of its edges (MLP-4 unrolled), add into kg
__global__ void __launch_bounds__(256) agg_kernel() {
    int gw = (blockIdx.x * blockDim.x + threadIdx.x) >> 5;
    int lane = threadIdx.x & 31;
    if (gw >= NE) return;
    int off = g_off[gw], end = g_off[gw + 1];
    float a0 = 0.f, a1 = 0.f, a2 = 0.f, a3 = 0.f;
    for (int b = off; b < end; b += 32) {
        int n = min(32, end - b);
        int pk = (b + lane < end) ? g_elist[b + lane] : 0;
        int j = 0;
        for (; j + 4 <= n; j += 4) {
            int p0 = __shfl_sync(0xFFFFFFFFu, pk, j);
            int p1 = __shfl_sync(0xFFFFFFFFu, pk, j + 1);
            int p2 = __shfl_sync(0xFFFFFFFFu, pk, j + 2);
            int p3 = __shfl_sync(0xFFFFFFFFu, pk, j + 3);
            float4 v0 = *(const float4*)(g_W + ((size_t)(p0 >> 16) * NE + (p0 & 0xFFFF)) * D + lane * 4);
            float4 v1 = *(const float4*)(g_W + ((size_t)(p1 >> 16) * NE + (p1 & 0xFFFF)) * D + lane * 4);
            float4 v2 = *(const float4*)(g_W + ((size_t)(p2 >> 16) * NE + (p2 & 0xFFFF)) * D + lane * 4);
            float4 v3 = *(const float4*)(g_W + ((size_t)(p3 >> 16) * NE + (p3 & 0xFFFF)) * D + lane * 4);
            float n0 = 1.f / fmaxf((float)g_cnt[gw * NREL + (p0 >> 16)], 1.f);
            float n1 = 1.f / fmaxf((float)g_cnt[gw * NREL + (p1 >> 16)], 1.f);
            float n2 = 1.f / fmaxf((float)g_cnt[gw * NREL + (p2 >> 16)], 1.f);
            float n3 = 1.f / fmaxf((float)g_cnt[gw * NREL + (p3 >> 16)], 1.f);
            a0 = fmaf(v0.x, n0, a0); a1 = fmaf(v0.y, n0, a1); a2 = fmaf(v0.z, n0, a2); a3 = fmaf(v0.w, n0, a3);
            a0 = fmaf(v1.x, n1, a0); a1 = fmaf(v1.y, n1, a1); a2 = fmaf(v1.z, n1, a2); a3 = fmaf(v1.w, n1, a3);
            a0 = fmaf(v2.x, n2, a0); a1 = fmaf(v2.y, n2, a1); a2 = fmaf(v2.z, n2, a2); a3 = fmaf(v2.w, n2, a3);
            a0 = fmaf(v3.x, n3, a0); a1 = fmaf(v3.y, n3, a1); a2 = fmaf(v3.z, n3, a2); a3 = fmaf(v3.w, n3, a3);
        }
        for (; j < n; j++) {
            int p = __shfl_sync(0xFFFFFFFFu, pk, j);
            int src = p & 0xFFFF, r = p >> 16;
            float norm = 1.f / fmaxf((float)g_cnt[gw * NREL + r], 1.f);
            float4 v = *(const float4*)(g_W + ((size_t)r * NE + src) * D + lane * 4);
            a0 = fmaf(v.x, norm, a0); a1 = fmaf(v.y, norm, a1);
            a2 = fmaf(v.z, norm, a2); a3 = fmaf(v.w, norm, a3);
        }
    }
    float* o = g_kg + (size_t)gw * D + lane * 4;
    float4 cur = *(float4*)o;
    *(float4*)o = make_float4(cur.x + a0, cur.y + a1, cur.z + a2, cur.w + a3);
}

// ---------------- encoder ----------------
__global__ void __launch_bounds__(256) embed_kernel(const int* __restrict__ tokens,
                                                    const float* __restrict__ tok_emb,
                                                    const float* __restrict__ pos_emb) {
    int i = blockIdx.x * blockDim.x + threadIdx.x;
    int d = i & (D - 1);
    int bl = i >> 7;
    int l = bl & (LSEQ - 1);
    int tk = tokens[bl];
    g_x[i] = tok_emb[(size_t)tk * D + d] * 11.3137084989847603904f + pos_emb[l * D + d];
}

// ---- 3xTF32 tensor-core GEMM, pre-split smem + prefetch double buffer ----
__global__ void __launch_bounds__(256) gemm_tc_kernel(const float* __restrict__ Bw,
                                                      const float* __restrict__ bias,
                                                      int asel, int csel,
                                                      int M, int N, int K, int relu,
                                                      int qkv_mode) {
    int n0;
    if (qkv_mode) { Bw += (size_t)blockIdx.y * D * D; csel += blockIdx.y; n0 = 0; }
    else n0 = blockIdx.y * 128;
    const float* __restrict__ A = g_bufs[asel];
    float* __restrict__ C = g_bufs[csel];
    __shared__ unsigned Ah[16][136], Al[16][136];   // [k][m] tf32 hi/lo
    __shared__ unsigned Bh[16][136], Bl[16][136];   // [k][n]
    int m0 = blockIdx.x * 128;
    int tid = threadIdx.x;
    int wid = tid >> 5, lane = tid & 31;
    int wm = wid & 3, wn = wid >> 2;
    int g = lane >> 2, t4 = lane & 3;

    float acc[2][8][4];
    #pragma unroll
    for (int i = 0; i < 2; i++)
        #pragma unroll
        for (int j = 0; j < 8; j++)
            #pragma unroll
            for (int q = 0; q < 4; q++) acc[i][j][q] = 0.f;

    int ar = tid >> 1, ak = (tid & 1) * 8;
    int bk = tid >> 4, bn = (tid & 15) * 8;

    // prefetch tile 0
    float4 pa0, pa1, pb0, pb1;
    {
        const float* ap = A + (size_t)(m0 + ar) * K + ak;
        pa0 = *(const float4*)ap; pa1 = *(const float4*)(ap + 4);
        const float* bp = Bw + (size_t)bk * N + n0 + bn;
        pb0 = *(const float4*)bp; pb1 = *(const float4*)(bp + 4);
    }

    for (int kc = 0; kc < K; kc += 16) {
        // split-store prefetched regs into smem
        {
            float av[8] = {pa0.x, pa0.y, pa0.z, pa0.w, pa1.x, pa1.y, pa1.z, pa1.w};
            #pragma unroll
            for (int i = 0; i < 8; i++) {
                unsigned hi, lo; tf_split(av[i], hi, lo);
                Ah[ak + i][ar] = hi; Al[ak + i][ar] = lo;
            }
            float bv[8] = {pb0.x, pb0.y, pb0.z, pb0.w, pb1.x, pb1.y, pb1.z, pb1.w};
            unsigned h4[8], l4[8];
            #pragma unroll
            for (int i = 0; i < 8; i++) tf_split(bv[i], h4[i], l4[i]);
            *(uint4*)&Bh[bk][bn]     = make_uint4(h4[0], h4[1], h4[2], h4[3]);
            *(uint4*)&Bh[bk][bn + 4] = make_uint4(h4[4], h4[5], h4[6], h4[7]);
            *(uint4*)&Bl[bk][bn]     = make_uint4(l4[0], l4[1], l4[2], l4[3]);
            *(uint4*)&Bl[bk][bn + 4] = make_uint4(l4[4], l4[5], l4[6], l4[7]);
        }
        __syncthreads();
        if (kc + 16 < K) {   // prefetch next tile (overlaps with compute)
            const float* ap = A + (size_t)(m0 + ar) * K + kc + 16 + ak;
            pa0 = *(const float4*)ap; pa1 = *(const float4*)(ap + 4);
            const float* bp = Bw + (size_t)(kc + 16 + bk) * N + n0 + bn;
            pb0 = *(const float4*)bp; pb1 = *(const float4*)(bp + 4);
        }
        #pragma unroll
        for (int ks = 0; ks < 16; ks += 8) {
            unsigned ah[2][4], al_[2][4];
            #pragma unroll
            for (int mf = 0; mf < 2; mf++) {
                int mm = wm * 32 + mf * 16;
                ah[mf][0] = Ah[ks + t4    ][mm + g    ];  al_[mf][0] = Al[ks + t4    ][mm + g    ];
                ah[mf][1] = Ah[ks + t4    ][mm + g + 8];  al_[mf][1] = Al[ks + t4    ][mm + g + 8];
                ah[mf][2] = Ah[ks + t4 + 4][mm + g    ];  al_[mf][2] = Al[ks + t4 + 4][mm + g    ];
                ah[mf][3] = Ah[ks + t4 + 4][mm + g + 8];  al_[mf][3] = Al[ks + t4 + 4][mm + g + 8];
            }
            #pragma unroll
            for (int nf = 0; nf < 8; nf++) {
                int nn = wn * 64 + nf * 8 + g;
                unsigned bh2[2] = {Bh[ks + t4][nn], Bh[ks + t4 + 4][nn]};
                unsigned bl2[2] = {Bl[ks + t4][nn], Bl[ks + t4 + 4][nn]};
                #pragma unroll
                for (int mf = 0; mf < 2; mf++) {
                    mma_tf32(acc[mf][nf], al_[mf], bh2);
                    mma_tf32(acc[mf][nf], ah[mf], bl2);
                    mma_tf32(acc[mf][nf], ah[mf], bh2);
                }
            }
        }
        __syncthreads();
    }
    #pragma unroll
    for (int mf = 0; mf < 2; mf++) {
        int r0 = m0 + wm * 32 + mf * 16 + g;
        #pragma unroll
        for (int nf = 0; nf < 8; nf++) {
            int c0 = n0 + wn * 64 + nf * 8 + t4 * 2;
            float bb0 = bias ? bias[c0] : 0.f;
            float bb1 = bias ? bias[c0 + 1] : 0.f;
            float v0 = acc[mf][nf][0] + bb0, v1 = acc[mf][nf][1] + bb1;
            float v2 = acc[mf][nf][2] + bb0, v3 = acc[mf][nf][3] + bb1;
            if (relu) {
                v0 = fmaxf(v0, 0.f); v1 = fmaxf(v1, 0.f);
                v2 = fmaxf(v2, 0.f); v3 = fmaxf(v3, 0.f);
            }
            *(float2*)&C[(size_t)r0 * N + c0]       = make_float2(v0, v1);
            *(float2*)&C[(size_t)(r0 + 8) * N + c0] = make_float2(v2, v3);
        }
    }
}

// ---- tensor-core attention scores (3xTF32) ----
__global__ void __launch_bounds__(256) attn_scores_tc(const int* __restrict__ tokens) {
    int bh = blockIdx.x;
    int b = bh >> 1, h = bh & 1;
    int q0 = blockIdx.y * 64, k0 = blockIdx.z * 64;
    __shared__ float Qs[64][68];
    __shared__ float Ks[64][68];
    int tid = threadIdx.x;
    int r = tid >> 2, dg = (tid & 3) * 16;
    {
        const float* qp = g_q + (size_t)(b * LSEQ + q0 + r) * D + h * DH + dg;
        const float* kp = g_k + (size_t)(b * LSEQ + k0 + r) * D + h * DH + dg;
        #pragma unroll
        for (int u = 0; u < 4; u++) {
            *(float4*)&Qs[r][dg + u * 4] = *(const float4*)(qp + u * 4);
            *(float4*)&Ks[r][dg + u * 4] = *(const float4*)(kp + u * 4);
        }
    }
    __syncthreads();
    int wid = tid >> 5, lane = tid & 31;
    int wm = wid & 3, wn = wid >> 2;
    int g = lane >> 2, t4 = lane & 3;
    int m0 = wm * 16;

    float acc[4][4];
    #pragma unroll
    for (int j = 0; j < 4; j++)
        #pragma unroll
        for (int q = 0; q < 4; q++) acc[j][q] = 0.f;

    #pragma unroll
    for (int ks = 0; ks < 64; ks += 8) {
        unsigned ah[4], al[4];
        tf_split(Qs[m0 + g    ][ks + t4    ], ah[0], al[0]);
        tf_split(Qs[m0 + g + 8][ks + t4    ], ah[1], al[1]);
        tf_split(Qs[m0 + g    ][ks + t4 + 4], ah[2], al[2]);
        tf_split(Qs[m0 + g + 8][ks + t4 + 4], ah[3], al[3]);
        #pragma unroll
        for (int nf = 0; nf < 4; nf++) {
            int nn = wn * 32 + nf * 8 + g;
            unsigned bh2[2], bl2[2];
            tf_split(Ks[nn][ks + t4    ], bh2[0], bl2[0]);
            tf_split(Ks[nn][ks + t4 + 4], bh2[1], bl2[1]);
            mma_tf32(acc[nf], al, bh2);
            mma_tf32(acc[nf], ah, bl2);
            mma_tf32(acc[nf], ah, bh2);
        }
    }
    int row0 = bh * LSEQ + q0 + m0 + g;
    #pragma unroll
    for (int nf = 0; nf < 4; nf++) {
        int c0 = k0 + wn * 32 + nf * 8 + t4 * 2;
        float mb0 = (tokens[b * LSEQ + c0] != 0) ? 0.f : NEGV;
        float mb1 = (tokens[b * LSEQ + c0 + 1] != 0) ? 0.f : NEGV;
        *(float2*)&g_sc[(size_t)row0 * LSEQ + c0] =
            make_float2(acc[nf][0] * 0.125f + mb0, acc[nf][1] * 0.125f + mb1);
        *(float2*)&g_sc[(size_t)(row0 + 8) * LSEQ + c0] =
            make_float2(acc[nf][2] * 0.125f + mb0, acc[nf][3] * 0.125f + mb1);
    }
}

__global__ void __launch_bounds__(128) softmax_kernel() {
    int row = blockIdx.x * 4 + (threadIdx.x >> 5);
    int lane = threadIdx.x & 31;
    float* p = g_sc + (size_t)row * LSEQ;
    float v[8];
    float m = -INFINITY;
    #pragma unroll
    for (int i = 0; i < 8; i++) { v[i] = p[lane + 32 * i]; m = fmaxf(m, v[i]); }
    m = warp_max(m);
    float s = 0.f;
    #pragma unroll
    for (int i = 0; i < 8; i++) { v[i] = expf(v[i] - m); s += v[i]; }
    s = warp_sum(s);
    float inv = 1.f / s;
    #pragma unroll
    for (int i = 0; i < 8; i++) p[lane + 32 * i] = v[i] * inv;
}

// ---- tensor-core AV (3xTF32) ----
__global__ void __launch_bounds__(256) attn_av_tc() {
    int bh = blockIdx.x;
    int b = bh >> 1, h = bh & 1;
    int l0 = blockIdx.y * 128;
    __shared__ float Ps[128][36];
    __shared__ float Vs[32][68];
    int tid = threadIdx.x;
    int wid = tid >> 5, lane = tid & 31;
    int wm = wid & 3, wn = wid >> 2;
    int g = lane >> 2, t4 = lane & 3;

    float acc[2][4][4];
    #pragma unroll
    for (int i = 0; i < 2; i++)
        #pragma unroll
        for (int j = 0; j < 4; j++)
            #pragma unroll
            for (int q = 0; q < 4; q++) acc[i][j][q] = 0.f;

    int pr = tid >> 1, pk = (tid & 1) * 16;
    int vr = tid >> 3, vd = (tid & 7) * 8;

    for (int kc = 0; kc < 8; kc++) {
        const float* pp = g_sc + (size_t)(bh * LSEQ + l0 + pr) * LSEQ + kc * 32 + pk;
        #pragma unroll
        for (int u = 0; u < 4; u++)
            *(float4*)&Ps[pr][pk + u * 4] = *(const float4*)(pp + u * 4);
        const float* vp = g_v + (size_t)(b * LSEQ + kc * 32 + vr) * D + h * DH + vd;
        #pragma unroll
        for (int u = 0; u < 2; u++)
            *(float4*)&Vs[vr][vd + u * 4] = *(const float4*)(vp + u * 4);
        __syncthreads();
        #pragma unroll
        for (int ks = 0; ks < 32; ks += 8) {
            unsigned ah[2][4], al[2][4];
            #pragma unroll
            for (int mf = 0; mf < 2; mf++) {
                int mm = wm * 32 + mf * 16;
                tf_split(Ps[mm + g    ][ks + t4    ], ah[mf][0], al[mf][0]);
                tf_split(Ps[mm + g + 8][ks + t4    ], ah[mf][1], al[mf][1]);
                tf_split(Ps[mm + g    ][ks + t4 + 4], ah[mf][2], al[mf][2]);
                tf_split(Ps[mm + g + 8][ks + t4 + 4], ah[mf][3], al[mf][3]);
            }
            #pragma unroll
            for (int nf = 0; nf < 4; nf++) {
                int nn = wn * 32 + nf * 8 + g;
                unsigned bh2[2], bl2[2];
                tf_split(Vs[ks + t4    ][nn], bh2[0], bl2[0]);
                tf_split(Vs[ks + t4 + 4][nn], bh2[1], bl2[1]);
                #pragma unroll
                for (int mf = 0; mf < 2; mf++) {
                    mma_tf32(acc[mf][nf], al[mf], bh2);
                    mma_tf32(acc[mf][nf], ah[mf], bl2);
                    mma_tf32(acc[mf][nf], ah[mf], bh2);
                }
            }
        }
        __syncthreads();
    }
    #pragma unroll
    for (int mf = 0; mf < 2; mf++) {
        int r0 = b * LSEQ + l0 + wm * 32 + mf * 16 + g;
        #pragma unroll
        for (int nf = 0; nf < 4; nf++) {
            int c0 = h * DH + wn * 32 + nf * 8 + t4 * 2;
            *(float2*)&g_ao[(size_t)r0 * D + c0] = make_float2(acc[mf][nf][0], acc[mf][nf][1]);
            *(float2*)&g_ao[(size_t)(r0 + 8) * D + c0] = make_float2(acc[mf][nf][2], acc[mf][nf][3]);
        }
    }
}

__global__ void __launch_bounds__(128) add_ln_kernel(const float* __restrict__ g,
                                                     const float* __restrict__ b) {
    int row = blockIdx.x, tid = threadIdx.x;
    int w = tid >> 5, lane = tid & 31;
    float v = g_x[(size_t)row * D + tid] + g_tmp[(size_t)row * D + tid];
    float s = warp_sum(v);
    float s2 = warp_sum(v * v);
    __shared__ float ws[4], ws2[4];
    if (lane == 0) { ws[w] = s; ws2[w] = s2; }
    __syncthreads();
    s = ws[0] + ws[1] + ws[2] + ws[3];
    s2 = ws2[0] + ws2[1] + ws2[2] + ws2[3];
    float m = s * (1.f / D);
    float var = s2 * (1.f / D) - m * m;
    float inv = rsqrtf(var + 1e-5f);
    g_x[(size_t)row * D + tid] = (v - m) * inv * g[tid] + b[tid];
}

// ---------------- pooling / gate / final ----------------
__global__ void __launch_bounds__(128) tok_pool_kernel(const int* __restrict__ tokens,
                                                       const float* __restrict__ vvec) {
    int b = blockIdx.x, tid = threadIdx.x;
    int w = tid >> 5, lane = tid & 31;
    __shared__ float s_s[LSEQ];
    __shared__ float red[4];
    for (int l = w; l < LSEQ; l += 4) {
        float val = 0.f;
        #pragma unroll
        for (int d = lane; d < D; d += 32)
            val += tanhf(g_ffn[((size_t)(b * LSEQ + l)) * D + d]) * vvec[d];
        val = warp_sum(val);
        if (lane == 0) s_s[l] = (tokens[b * LSEQ + l] != 0) ? val : NEGV;
    }
    __syncthreads();
    float m = fmaxf(s_s[tid], s_s[tid + 128]);
    m = warp_max(m);
    if (lane == 0) red[w] = m;
    __syncthreads();
    m = fmaxf(fmaxf(red[0], red[1]), fmaxf(red[2], red[3]));
    __syncthreads();
    float e0 = expf(s_s[tid] - m), e1 = expf(s_s[tid + 128] - m);
    float ssum = warp_sum(e0 + e1);
    if (lane == 0) red[w] = ssum;
    __syncthreads();
    ssum = red[0] + red[1] + red[2] + red[3];
    float inv = 1.f / ssum;
    __syncthreads();
    s_s[tid] = e0 * inv; s_s[tid + 128] = e1 * inv;
    __syncthreads();
    float acc = 0.f;
    for (int l = 0; l < LSEQ; l++)
        acc = fmaf(s_s[l], g_x[((size_t)(b * LSEQ + l)) * D + tid], acc);
    g_trep[b * D + tid] = acc;
}

__global__ void __launch_bounds__(128) ent_pool_kernel(const int* __restrict__ ctx,
                                                       const float* __restrict__ Wa,
                                                       const float* __restrict__ ba,
                                                       const float* __restrict__ vvec) {
    int b = blockIdx.x, tid = threadIdx.x;
    int w = tid >> 5, lane = tid & 31;
    __shared__ float h_s[NCTX][D];
    __shared__ float s_s[NCTX];
    __shared__ int cs[NCTX];
    if (tid < NCTX) cs[tid] = ctx[b * NCTX + tid];
    __syncthreads();
    for (int j = 0; j < NCTX; j++)
        h_s[j][tid] = g_kg[(size_t)cs[j] * D + tid];
    __syncthreads();
    for (int j = w; j < NCTX; j += 4) {
        float val = 0.f;
        for (int d = lane; d < D; d += 32) {
            float acc = ba[d];
            #pragma unroll 8
            for (int kk = 0; kk < D; kk++)
                acc = fmaf(h_s[j][kk], Wa[kk * D + d], acc);
            val += tanhf(acc) * vvec[d];
        }
        val = warp_sum(val);
        if (lane == 0) s_s[j] = (cs[j] != 0) ? val : NEGV;
    }
    __syncthreads();
    if (w == 0) {
        float sv = s_s[lane];
        float m = warp_max(sv);
        float e = expf(sv - m);
        float ssum = warp_sum(e);
        s_s[lane] = e / ssum;
    }
    __syncthreads();
    float acc = 0.f;
    #pragma unroll
    for (int j = 0; j < NCTX; j++) acc = fmaf(s_s[j], h_s[j][tid], acc);
    g_erep[b * D + tid] = acc;
}

__global__ void __launch_bounds__(128) gate_kernel(const float* __restrict__ Wg,
                                                   const float* __restrict__ bg) {
    int b = blockIdx.x, tid = threadIdx.x;
    __shared__ float cat[2 * D];
    cat[tid] = g_trep[b * D + tid];
    cat[D + tid] = g_erep[b * D + tid];
    __syncthreads();
    float acc = bg[tid];
    #pragma unroll 8
    for (int j = 0; j < 2 * D; j++) acc = fmaf(cat[j], Wg[j * D + tid], acc);
    float sg = 1.f / (1.f + expf(-acc));
    g_user[b * D + tid] = sg * cat[tid] + (1.f - sg) * cat[D + tid];
}

__global__ void __launch_bounds__(256) final_kernel(float* __restrict__ out) {
    __shared__ float kg_s[128][17];
    __shared__ float user_t[D][BATCH];
    int n0 = blockIdx.x * 128, tid = threadIdx.x;
    for (int i = tid; i < D * BATCH; i += 256) {
        int d = i >> 6, bb = i & 63;
        user_t[d][bb] = g_user[bb * D + d];
    }
    int tn = tid >> 3, tb = tid & 7;
    float acc[4][8];
    #pragma unroll
    for (int i = 0; i < 4; i++)
        #pragma unroll
        for (int j = 0; j < 8; j++) acc[i][j] = 0.f;
    for (int dc = 0; dc < D; dc += 16) {
        __syncthreads();
        for (int i = tid; i < 128 * 16; i += 256) {
            int nl = i >> 4, dd = i & 15;
            int n = n0 + nl;
            kg_s[nl][dd] = (n < NE) ? g_kg[(size_t)n * D + dc + dd] : 0.f;
        }
        __syncthreads();
        #pragma unroll
        for (int dd = 0; dd < 16; dd++) {
            float kv[4], uv[8];
            #pragma unroll
            for (int i = 0; i < 4; i++) kv[i] = kg_s[tn * 4 + i][dd];
            #pragma unroll
            for (int j = 0; j < 8; j++) uv[j] = user_t[dc + dd][tb * 8 + j];
            #pragma unroll
            for (int i = 0; i < 4; i++)
                #pragma unroll
                for (int j = 0; j < 8; j++) acc[i][j] = fmaf(kv[i], uv[j], acc[i][j]);
        }
    }
    #pragma unroll
    for (int i = 0; i < 4; i++) {
        int n = n0 + tn * 4 + i;
        if (n < NE) {
            #pragma unroll
            for (int j = 0; j < 8; j++)
                out[(size_t)(tb * 8 + j) * NE + n] = acc[i][j];
        }
    }
}

// ---------------- launch ----------------
extern "C" void kernel_launch(void* const* d_in, const int* in_sizes, int n_in,
                              void* d_out, int out_size) {
    const int*   edge_idx = (const int*)d_in[0];
    const int*   edge_type = (const int*)d_in[1];
    const int*   ctx_ent  = (const int*)d_in[2];
    const int*   ctx_tok  = (const int*)d_in[3];
    const float* basis    = (const float*)d_in[4];
    const float* comp     = (const float*)d_in[5];
    const float* root     = (const float*)d_in[6];
    const float* rgcn_b   = (const float*)d_in[7];
    const float* tok_emb  = (const float*)d_in[8];
    const float* pos_emb  = (const float*)d_in[9];
    const float* Wqkv     = (const float*)d_in[10];
    const float* Wo       = (const float*)d_in[11];
    const float* ln1_g    = (const float*)d_in[12];
    const float* ln1_b    = (const float*)d_in[13];
    const float* ln2_g    = (const float*)d_in[14];
    const float* ln2_b    = (const float*)d_in[15];
    const float* W1       = (const float*)d_in[16];
    const float* b1       = (const float*)d_in[17];
    const float* W2       = (const float*)d_in[18];
    const float* b2       = (const float*)d_in[19];
    const float* ent_Wa   = (const float*)d_in[20];
    const float* ent_ba   = (const float*)d_in[21];
    const float* ent_v    = (const float*)d_in[22];
    const float* tok_Wa   = (const float*)d_in[23];
    const float* tok_ba   = (const float*)d_in[24];
    const float* tok_v    = (const float*)d_in[25];
    const float* Wg       = (const float*)d_in[26];
    const float* bg       = (const float*)d_in[27];
    float* out = (float*)d_out;

    init_ptrs_kernel<<<1, 1>>>();

    // --- RGCN (CSR, no atomics on kg) ---
    zero_cnt_kernel<<<(NE * NREL + 255) / 256, 256>>>();
    rgcn_w_kernel<<<NE, 128>>>(basis, comp, root, rgcn_b);
    count_kernel<<<(NEDGE + 255) / 256, 256>>>(edge_idx, edge_type);
    scan_kernel<<<1, 1024>>>();
    fill_kernel<<<(NEDGE + 255) / 256, 256>>>(edge_idx, edge_type);
    agg_kernel<<<(NE * 32 + 255) / 256, 256>>>();

    // --- encoder ---
    embed_kernel<<<(BATCH * LSEQ * D) / 256, 256>>>(ctx_tok, tok_emb, pos_emb);
    const int M = BATCH * LSEQ;  // 16384
    for (int l = 0; l < NLAY; l++) {
        gemm_tc_kernel<<<dim3(M / 128, 3), 256>>>(Wqkv + (size_t)l * 3 * D * D, nullptr, BUF_X, BUF_Q, M, D, D, 0, 1);
        attn_scores_tc<<<dim3(BATCH * NHEAD, LSEQ / 64, LSEQ / 64), 256>>>(ctx_tok);
        softmax_kernel<<<(BATCH * NHEAD * LSEQ) / 4, 128>>>();
        attn_av_tc<<<dim3(BATCH * NHEAD, LSEQ / 128), 256>>>();
        gemm_tc_kernel<<<dim3(M / 128, 1), 256>>>(Wo + (size_t)l * D * D, nullptr, BUF_AO, BUF_TMP, M, D, D, 0, 0);
        add_ln_kernel<<<M, 128>>>(ln1_g + l * D, ln1_b + l * D);
        gemm_tc_kernel<<<dim3(M / 128, FFND / 128), 256>>>(W1 + (size_t)l * D * FFND, b1 + l * FFND, BUF_X, BUF_FFN, M, FFND, D, 1, 0);
        gemm_tc_kernel<<<dim3(M / 128, 1), 256>>>(W2 + (size_t)l * FFND * D, b2 + l * D, BUF_FFN, BUF_TMP, M, D, FFND, 0, 0);
        add_ln_kernel<<<M, 128>>>(ln2_g + l * D, ln2_b + l * D);
    }

    // --- pooling / gate / score ---
    gemm_tc_kernel<<<dim3(M / 128, 1), 256>>>(tok_Wa, tok_ba, BUF_X, BUF_FFN, M, D, D, 0, 0);
    tok_pool_kernel<<<BATCH, 128>>>(ctx_tok, tok_v);
    ent_pool_kernel<<<BATCH, 128>>>(ctx_ent, ent_Wa, ent_ba, ent_v);
    gate_kernel<<<BATCH, 128>>>(Wg, bg);
    final_kernel<<<(NE + 127) / 128, 256>>>(out);
}